// round 1
// baseline (speedup 1.0000x reference)
#include <cuda_runtime.h>
#include <math.h>

#define NB 2
#define NT 2048
#define ND 1024
#define NH 16
#define NHD 64
#define NBT (NB*NT)

// ---------------- scratch (static device globals; no allocations) ----------
__device__ float g_Q[(size_t)NBT*ND];
__device__ float g_K[(size_t)NBT*ND];
__device__ float g_V[(size_t)NBT*ND];     // V' = X @ Wv'
__device__ float g_O[(size_t)NBT*ND];     // attention output
__device__ float g_rope[(size_t)NT*NHD];
__device__ float g_R[NHD*NHD];            // rope^T @ rope  (64x64)
__device__ float g_Wvp[(size_t)ND*ND];    // Wv @ blockdiag(R)

// ---------------- rope table -----------------------------------------------
__global__ void rope_build() {
    int g = blockIdx.x * blockDim.x + threadIdx.x;
    if (g >= NT * NHD) return;
    int s = g >> 6, i = g & 63, k = i & 31;
    double inv = exp(-(double)k * (log(10000.0) / 32.0));
    double ph = (double)s * inv;
    g_rope[g] = (i < 32) ? (float)cos(ph) : (float)sin(ph);
}

// R[i][j] = sum_s rope[s,i]*rope[s,j]
__global__ void compute_R() {
    int g = blockIdx.x * blockDim.x + threadIdx.x;   // 4096 threads
    int i = g >> 6, j = g & 63;
    float acc = 0.f;
    for (int s = 0; s < NT; s++)
        acc += g_rope[s * 64 + i] * g_rope[s * 64 + j];
    g_R[i * 64 + j] = acc;
}

// Wvp[d][h*64+j] = sum_i Wv[d][h*64+i] * R[i][j]
__global__ void fold_wv(const float* __restrict__ Wv) {
    int g = blockIdx.x * blockDim.x + threadIdx.x;   // D*D threads
    int j = g & 63;
    int h = (g >> 6) & (NH - 1);
    int d = g >> 10;
    const float* wrow = Wv + (size_t)d * ND + h * 64;
    float acc = 0.f;
#pragma unroll 8
    for (int i = 0; i < 64; i++)
        acc += wrow[i] * g_R[i * 64 + j];
    g_Wvp[g] = acc;
}

// ---------------- generic SGEMM: C = A(MxK) @ B(KxN) (+bias) ---------------
// 128x128 tile, BK=8, 256 threads, 8x8 per thread (2x2 of 4x4 quadrants)
template<bool HAS_BIAS>
__global__ __launch_bounds__(256) void sgemm128(
    const float* __restrict__ A, const float* __restrict__ Bm,
    float* __restrict__ C, const float* __restrict__ bias,
    int M, int N, int K)
{
    __shared__ float As[8][132];   // [k][m], padded (conflict-free STS/LDS)
    __shared__ float Bs[8][128];   // [k][n]
    const int tid = threadIdx.x;
    const int bm = blockIdx.y, bn = blockIdx.x;
    const int arow = tid >> 1, acol = (tid & 1) * 4;
    const int brow = tid >> 5, bcol = (tid & 31) * 4;
    const float* Ap = A + (size_t)(bm * 128 + arow) * K + acol;
    const float* Bp = Bm + (size_t)brow * N + bn * 128 + bcol;
    const int tr = tid >> 4, tc = tid & 15;

    float acc[2][2][4][4];
#pragma unroll
    for (int a = 0; a < 2; a++)
#pragma unroll
        for (int b = 0; b < 2; b++)
#pragma unroll
            for (int i = 0; i < 4; i++)
#pragma unroll
                for (int j = 0; j < 4; j++) acc[a][b][i][j] = 0.f;

    for (int k0 = 0; k0 < K; k0 += 8) {
        float4 av = *(const float4*)Ap; Ap += 8;
        float4 bv = *(const float4*)Bp; Bp += (size_t)8 * N;
        As[acol + 0][arow] = av.x;
        As[acol + 1][arow] = av.y;
        As[acol + 2][arow] = av.z;
        As[acol + 3][arow] = av.w;
        *(float4*)&Bs[brow][bcol] = bv;
        __syncthreads();
#pragma unroll
        for (int k = 0; k < 8; k++) {
            float a0[4], a1[4], b0[4], b1[4];
            *(float4*)a0 = *(const float4*)&As[k][tr * 4];
            *(float4*)a1 = *(const float4*)&As[k][64 + tr * 4];
            *(float4*)b0 = *(const float4*)&Bs[k][tc * 4];
            *(float4*)b1 = *(const float4*)&Bs[k][64 + tc * 4];
#pragma unroll
            for (int i = 0; i < 4; i++)
#pragma unroll
                for (int j = 0; j < 4; j++) {
                    acc[0][0][i][j] += a0[i] * b0[j];
                    acc[0][1][i][j] += a0[i] * b1[j];
                    acc[1][0][i][j] += a1[i] * b0[j];
                    acc[1][1][i][j] += a1[i] * b1[j];
                }
        }
        __syncthreads();
    }

#pragma unroll
    for (int ri = 0; ri < 2; ri++)
#pragma unroll
        for (int i = 0; i < 4; i++) {
            int row = bm * 128 + ri * 64 + tr * 4 + i;
            float* Crow = C + (size_t)row * N + bn * 128;
#pragma unroll
            for (int ci = 0; ci < 2; ci++) {
                int col = ci * 64 + tc * 4;
                float4 v;
                v.x = acc[ri][ci][i][0];
                v.y = acc[ri][ci][i][1];
                v.z = acc[ri][ci][i][2];
                v.w = acc[ri][ci][i][3];
                if (HAS_BIAS) {
                    const float* bp = bias + bn * 128 + col;
                    v.x += bp[0]; v.y += bp[1]; v.z += bp[2]; v.w += bp[3];
                }
                *(float4*)&Crow[col] = v;
            }
        }
}

// ---------------- flash attention (Br=Bc=64, hd=64, fp32) ------------------
// grid: (T/64, B*H); 256 threads. smem: Qs,Ks,Vs,Ps each 64x68 floats.
#define FA_PAD 68
#define FA_SMEM (4 * 64 * FA_PAD * (int)sizeof(float))

__global__ __launch_bounds__(256) void flash_attn() {
    extern __shared__ float sm[];
    float (*Qs)[FA_PAD] = (float(*)[FA_PAD])(sm);
    float (*Ks)[FA_PAD] = (float(*)[FA_PAD])(sm + 64 * FA_PAD);
    float (*Vs)[FA_PAD] = (float(*)[FA_PAD])(sm + 2 * 64 * FA_PAD);
    float (*Ps)[FA_PAD] = (float(*)[FA_PAD])(sm + 3 * 64 * FA_PAD);

    const int tid = threadIdx.x;
    const int b = blockIdx.y >> 4, h = blockIdx.y & 15;
    const int q0 = blockIdx.x * 64;
    const size_t base = ((size_t)b * NT) * ND + (size_t)h * NHD;

    {
        int idx = tid;
#pragma unroll
        for (int it = 0; it < 4; it++, idx += 256) {
            int r = idx >> 4, c4 = (idx & 15) << 2;
            *(float4*)&Qs[r][c4] =
                *(const float4*)&g_Q[base + (size_t)(q0 + r) * ND + c4];
        }
    }

    const int r0 = (tid >> 4) << 2;   // 4 query rows owned by this thread
    const int lane16 = tid & 15;

    float m_i[4], l_i[4], oacc[4][4];
#pragma unroll
    for (int i = 0; i < 4; i++) {
        m_i[i] = -1e30f; l_i[i] = 0.f;
#pragma unroll
        for (int j = 0; j < 4; j++) oacc[i][j] = 0.f;
    }

    for (int kv0 = 0; kv0 < NT; kv0 += 64) {
        __syncthreads();   // protect Ks/Vs/Ps from previous iteration's readers
        {
            int idx = tid;
#pragma unroll
            for (int it = 0; it < 4; it++, idx += 256) {
                int r = idx >> 4, c4 = (idx & 15) << 2;
                size_t g = base + (size_t)(kv0 + r) * ND + c4;
                *(float4*)&Ks[r][c4] = *(const float4*)&g_K[g];
                *(float4*)&Vs[r][c4] = *(const float4*)&g_V[g];
            }
        }
        __syncthreads();

        // S = Q @ K^T  (thread: 4 rows x 4 interleaved cols)
        float s[4][4];
#pragma unroll
        for (int i = 0; i < 4; i++)
#pragma unroll
            for (int j = 0; j < 4; j++) s[i][j] = 0.f;

#pragma unroll
        for (int d = 0; d < 64; d += 4) {
            float4 qv[4], kv[4];
#pragma unroll
            for (int i = 0; i < 4; i++) qv[i] = *(const float4*)&Qs[r0 + i][d];
#pragma unroll
            for (int j = 0; j < 4; j++) kv[j] = *(const float4*)&Ks[lane16 + 16 * j][d];
#pragma unroll
            for (int i = 0; i < 4; i++)
#pragma unroll
                for (int j = 0; j < 4; j++)
                    s[i][j] += qv[i].x * kv[j].x + qv[i].y * kv[j].y +
                               qv[i].z * kv[j].z + qv[i].w * kv[j].w;
        }

        // online softmax per row (16 lanes share a row-group)
#pragma unroll
        for (int i = 0; i < 4; i++) {
#pragma unroll
            for (int j = 0; j < 4; j++) s[i][j] *= 0.125f;
            float rm = fmaxf(fmaxf(s[i][0], s[i][1]), fmaxf(s[i][2], s[i][3]));
            rm = fmaxf(rm, __shfl_xor_sync(0xffffffffu, rm, 1));
            rm = fmaxf(rm, __shfl_xor_sync(0xffffffffu, rm, 2));
            rm = fmaxf(rm, __shfl_xor_sync(0xffffffffu, rm, 4));
            rm = fmaxf(rm, __shfl_xor_sync(0xffffffffu, rm, 8));
            float mnew = fmaxf(m_i[i], rm);
            float corr = __expf(m_i[i] - mnew);
            m_i[i] = mnew;
            float rs = 0.f;
#pragma unroll
            for (int j = 0; j < 4; j++) {
                s[i][j] = __expf(s[i][j] - mnew);
                rs += s[i][j];
            }
            rs += __shfl_xor_sync(0xffffffffu, rs, 1);
            rs += __shfl_xor_sync(0xffffffffu, rs, 2);
            rs += __shfl_xor_sync(0xffffffffu, rs, 4);
            rs += __shfl_xor_sync(0xffffffffu, rs, 8);
            l_i[i] = l_i[i] * corr + rs;
#pragma unroll
            for (int j = 0; j < 4; j++) {
                oacc[i][j] *= corr;
                Ps[r0 + i][lane16 + 16 * j] = s[i][j];
            }
        }
        __syncthreads();

        // O += P @ V   (output dims blocked: cols lane16*4 .. +3)
#pragma unroll 8
        for (int c = 0; c < 64; c++) {
            float4 vv = *(const float4*)&Vs[c][lane16 << 2];
            float p0 = Ps[r0 + 0][c];
            float p1 = Ps[r0 + 1][c];
            float p2 = Ps[r0 + 2][c];
            float p3 = Ps[r0 + 3][c];
            oacc[0][0] += p0 * vv.x; oacc[0][1] += p0 * vv.y;
            oacc[0][2] += p0 * vv.z; oacc[0][3] += p0 * vv.w;
            oacc[1][0] += p1 * vv.x; oacc[1][1] += p1 * vv.y;
            oacc[1][2] += p1 * vv.z; oacc[1][3] += p1 * vv.w;
            oacc[2][0] += p2 * vv.x; oacc[2][1] += p2 * vv.y;
            oacc[2][2] += p2 * vv.z; oacc[2][3] += p2 * vv.w;
            oacc[3][0] += p3 * vv.x; oacc[3][1] += p3 * vv.y;
            oacc[3][2] += p3 * vv.z; oacc[3][3] += p3 * vv.w;
        }
    }

#pragma unroll
    for (int i = 0; i < 4; i++) {
        float inv = 1.f / l_i[i];
        float4 o;
        o.x = oacc[i][0] * inv; o.y = oacc[i][1] * inv;
        o.z = oacc[i][2] * inv; o.w = oacc[i][3] * inv;
        *(float4*)&g_O[base + (size_t)(q0 + r0 + i) * ND + ((size_t)lane16 << 2)] = o;
    }
}

// ---------------- host launcher --------------------------------------------
extern "C" void kernel_launch(void* const* d_in, const int* in_sizes, int n_in,
                              void* d_out, int out_size) {
    (void)in_sizes; (void)n_in; (void)out_size;
    const float* x  = (const float*)d_in[0];
    const float* Wq = (const float*)d_in[1];
    const float* Wk = (const float*)d_in[2];
    const float* Wv = (const float*)d_in[3];
    const float* Wo = (const float*)d_in[4];
    const float* bo = (const float*)d_in[5];
    float* out = (float*)d_out;

    float *Qp, *Kp, *Vp, *Op, *Wvpp;
    cudaGetSymbolAddress((void**)&Qp, g_Q);
    cudaGetSymbolAddress((void**)&Kp, g_K);
    cudaGetSymbolAddress((void**)&Vp, g_V);
    cudaGetSymbolAddress((void**)&Op, g_O);
    cudaGetSymbolAddress((void**)&Wvpp, g_Wvp);

    // rope / R / folded Wv
    rope_build<<<(NT * NHD + 255) / 256, 256>>>();
    compute_R<<<(NHD * NHD) / 256, 256>>>();
    fold_wv<<<(ND * ND) / 256, 256>>>(Wv);

    // projections: Q = X Wq, K = X Wk, V' = X Wv'
    dim3 gridP(ND / 128, NBT / 128);
    sgemm128<false><<<gridP, 256>>>(x, Wq, Qp, nullptr, NBT, ND, ND);
    sgemm128<false><<<gridP, 256>>>(x, Wk, Kp, nullptr, NBT, ND, ND);
    sgemm128<false><<<gridP, 256>>>(x, Wvpp, Vp, nullptr, NBT, ND, ND);

    // attention
    cudaFuncSetAttribute(flash_attn, cudaFuncAttributeMaxDynamicSharedMemorySize,
                         FA_SMEM);
    flash_attn<<<dim3(NT / 64, NB * NH), 256, FA_SMEM>>>();

    // output projection + bias
    sgemm128<true><<<gridP, 256>>>(Op, Wo, out, bo, NBT, ND, ND);
}

// round 3
// speedup vs baseline: 2.4115x; 2.4115x over previous
#include <cuda_runtime.h>
#include <cuda_bf16.h>
#include <cstdint>
#include <math.h>

#define NB 2
#define NT 2048
#define ND 1024
#define NH 16
#define NHD 64
#define NBT (NB*NT)
#define GK 3072            // split-bf16 stacked K
#define NCHUNK (GK/32)     // 96 chunks of BK=32
#define QKV_LD 3072

// ---------------- scratch ---------------------------------------------------
__device__ __nv_bfloat16 g_A2[(size_t)NBT*GK];
__device__ __nv_bfloat16 g_W2[(size_t)QKV_LD*GK];
__device__ __nv_bfloat16 g_Wo2[(size_t)ND*GK];
__device__ float g_QKV[(size_t)NBT*QKV_LD];
__device__ float g_O[(size_t)NBT*ND];
__device__ float g_rope[(size_t)NT*NHD];
__device__ float g_R[NHD*NHD];
__device__ float g_Wvp[(size_t)ND*ND];
// split Q/K/V for flash (Q pre-scaled by 0.125*log2e)
__device__ __nv_bfloat16 g_Qh[(size_t)NBT*ND], g_Ql[(size_t)NBT*ND];
__device__ __nv_bfloat16 g_Kh[(size_t)NBT*ND], g_Kl[(size_t)NBT*ND];
__device__ __nv_bfloat16 g_Vh[(size_t)NBT*ND], g_Vl[(size_t)NBT*ND];

// ---------------- helpers ---------------------------------------------------
__device__ __forceinline__ uint32_t smem_u32(const void* p) {
    uint32_t a;
    asm("{ .reg .u64 t; cvta.to.shared.u64 t, %1; cvt.u32.u64 %0, t; }"
        : "=r"(a) : "l"(p));
    return a;
}
#define CPA16(s, g) asm volatile("cp.async.cg.shared.global [%0], [%1], 16;\n" :: "r"(s), "l"(g))
#define CPCOMMIT()  asm volatile("cp.async.commit_group;\n" ::: "memory")
#define CPWAIT0()   asm volatile("cp.async.wait_group 0;\n" ::: "memory")
#define CPWAIT1()   asm volatile("cp.async.wait_group 1;\n" ::: "memory")

#define LDSM4(r, addr)                                                        \
    asm volatile("ldmatrix.sync.aligned.m8n8.x4.shared.b16 {%0,%1,%2,%3}, [%4];" \
                 : "=r"((r)[0]), "=r"((r)[1]), "=r"((r)[2]), "=r"((r)[3])     \
                 : "r"(addr))
#define LDSM4T(r, addr)                                                       \
    asm volatile("ldmatrix.sync.aligned.m8n8.x4.trans.shared.b16 {%0,%1,%2,%3}, [%4];" \
                 : "=r"((r)[0]), "=r"((r)[1]), "=r"((r)[2]), "=r"((r)[3])     \
                 : "r"(addr))
#define MMA_BF16(d, a, b)                                                     \
    asm volatile("mma.sync.aligned.m16n8k16.row.col.f32.bf16.bf16.f32 "       \
                 "{%0,%1,%2,%3},{%4,%5,%6,%7},{%8,%9},{%0,%1,%2,%3};"         \
                 : "+f"((d)[0]), "+f"((d)[1]), "+f"((d)[2]), "+f"((d)[3])     \
                 : "r"((a)[0]), "r"((a)[1]), "r"((a)[2]), "r"((a)[3]),        \
                   "r"((b)[0]), "r"((b)[1]))

__device__ __forceinline__ uint32_t pack_bf16(float lo, float hi) {
    uint32_t r;
    asm("cvt.rn.bf16x2.f32 %0, %1, %2;" : "=r"(r) : "f"(hi), "f"(lo));
    return r;
}

// ---------------- rope / R / fold -------------------------------------------
__global__ void rope_build() {
    int g = blockIdx.x * blockDim.x + threadIdx.x;
    if (g >= NT * NHD) return;
    int s = g >> 6, i = g & 63, k = i & 31;
    double inv = exp(-(double)k * (log(10000.0) / 32.0));
    double ph = (double)s * inv;
    g_rope[g] = (i < 32) ? (float)cos(ph) : (float)sin(ph);
}
__global__ void compute_R() {
    int g = blockIdx.x * blockDim.x + threadIdx.x;
    int i = g >> 6, j = g & 63;
    float acc = 0.f;
    for (int s = 0; s < NT; s++)
        acc += g_rope[s * 64 + i] * g_rope[s * 64 + j];
    g_R[i * 64 + j] = acc;
}
__global__ void fold_wv(const float* __restrict__ Wv) {
    int g = blockIdx.x * blockDim.x + threadIdx.x;
    int j = g & 63;
    int h = (g >> 6) & (NH - 1);
    int d = g >> 10;
    const float* wrow = Wv + (size_t)d * ND + h * 64;
    float acc = 0.f;
#pragma unroll 8
    for (int i = 0; i < 64; i++)
        acc += wrow[i] * g_R[i * 64 + j];
    g_Wvp[g] = acc;
}

// ---------------- split preparation -----------------------------------------
__global__ void prep_a(const float* __restrict__ X, __nv_bfloat16* __restrict__ A2, int Melems) {
    int g = blockIdx.x * blockDim.x + threadIdx.x;
    if (g >= Melems) return;
    int m = g >> 10, k = g & 1023;
    float v = X[g];
    __nv_bfloat16 hi = __float2bfloat16(v);
    __nv_bfloat16 lo = __float2bfloat16(v - __bfloat162float(hi));
    size_t base = (size_t)m * GK;
    A2[base + k] = hi;
    A2[base + 1024 + k] = lo;
    A2[base + 2048 + k] = hi;
}
__global__ void prep_w(const float* __restrict__ W, __nv_bfloat16* __restrict__ W2) {
    __shared__ float t[32][33];
    int k0 = blockIdx.y * 32, n0 = blockIdx.x * 32;
    int tx = threadIdx.x, ty = threadIdx.y;
#pragma unroll
    for (int i = 0; i < 32; i += 8)
        t[ty + i][tx] = W[(size_t)(k0 + ty + i) * ND + n0 + tx];
    __syncthreads();
#pragma unroll
    for (int i = 0; i < 32; i += 8) {
        int n = n0 + ty + i, k = k0 + tx;
        float v = t[tx][ty + i];
        __nv_bfloat16 hi = __float2bfloat16(v);
        __nv_bfloat16 lo = __float2bfloat16(v - __bfloat162float(hi));
        size_t b = (size_t)n * GK;
        W2[b + k] = hi;
        W2[b + 1024 + k] = hi;
        W2[b + 2048 + k] = lo;
    }
}
// split QKV (f32) -> bf16 hi/lo arrays; Q pre-scaled by 0.125*log2(e)
__global__ void qkv_split() {
    int g = blockIdx.x * blockDim.x + threadIdx.x;   // NBT*ND
    int m = g >> 10;
    size_t qi = (size_t)m * QKV_LD + (g & 1023);
    float q = g_QKV[qi] * 0.18033688011111772f;
    float k = g_QKV[qi + 1024];
    float v = g_QKV[qi + 2048];
    __nv_bfloat16 qh = __float2bfloat16(q);
    __nv_bfloat16 kh = __float2bfloat16(k);
    __nv_bfloat16 vh = __float2bfloat16(v);
    g_Qh[g] = qh; g_Ql[g] = __float2bfloat16(q - __bfloat162float(qh));
    g_Kh[g] = kh; g_Kl[g] = __float2bfloat16(k - __bfloat162float(kh));
    g_Vh[g] = vh; g_Vl[g] = __float2bfloat16(v - __bfloat162float(vh));
}

// ---------------- HMMA GEMM: C[M,Ncols] = A[M,GK] @ B[Ncols,GK]^T -----------
// 128x128x32 tile, 8 warps (2x4), 3-stage cp.async, smem stride 40 bf16.
#define GST 5120                       // elems per stage per operand (128*40)
#define GSMEM_B (6 * GST * 2)          // 61440 bytes

template<bool HAS_BIAS>
__global__ __launch_bounds__(256)
void gemm_mma(const __nv_bfloat16* __restrict__ A, const __nv_bfloat16* __restrict__ B,
              float* __restrict__ C, const float* __restrict__ bias, int Ncols)
{
    extern __shared__ __nv_bfloat16 gsm[];
    const uint32_t sbase = smem_u32(gsm);
    const int tid = threadIdx.x, lane = tid & 31, wid = tid >> 5;
    const int wm = wid >> 2, wn = wid & 3;
    const int m0 = blockIdx.y * 128, n0 = blockIdx.x * 128;
    const __nv_bfloat16* Ap = A + (size_t)m0 * GK;
    const __nv_bfloat16* Bp = B + (size_t)n0 * GK;

#define G_LOAD(st, ch)                                                        \
    do {                                                                      \
        uint32_t _sA = sbase + (st) * (GST * 2);                              \
        uint32_t _sB = sbase + (3 * GST + (st) * GST) * 2;                    \
        const __nv_bfloat16* _ag = Ap + (ch) * 32;                            \
        const __nv_bfloat16* _bg = Bp + (ch) * 32;                            \
        _Pragma("unroll")                                                     \
        for (int _i = 0; _i < 2; _i++) {                                      \
            int _idx = _i * 256 + tid;                                        \
            int _r = _idx >> 2, _sg = _idx & 3;                               \
            uint32_t _o = (uint32_t)(_r * 80 + _sg * 16);                     \
            CPA16(_sA + _o, _ag + (size_t)_r * GK + _sg * 8);                 \
            CPA16(_sB + _o, _bg + (size_t)_r * GK + _sg * 8);                 \
        }                                                                     \
        CPCOMMIT();                                                           \
    } while (0)

    float acc[4][4][4];
#pragma unroll
    for (int i = 0; i < 4; i++)
#pragma unroll
        for (int j = 0; j < 4; j++)
#pragma unroll
            for (int k = 0; k < 4; k++) acc[i][j][k] = 0.f;

    G_LOAD(0, 0);
    G_LOAD(1, 1);

    for (int c = 0; c < NCHUNK; c++) {
        if (c < NCHUNK - 1) CPWAIT1(); else CPWAIT0();
        __syncthreads();
        if (c + 2 < NCHUNK) G_LOAD((c + 2) % 3, c + 2);

        int st = c % 3;
        uint32_t sA = sbase + st * (GST * 2);
        uint32_t sB = sbase + (3 * GST + st * GST) * 2;
#pragma unroll
        for (int kk = 0; kk < 2; kk++) {
            uint32_t a[4][4], b[4][2];
#pragma unroll
            for (int mi = 0; mi < 4; mi++) {
                uint32_t ad = sA + (uint32_t)((wm * 64 + mi * 16 + (lane & 15)) * 80
                                              + kk * 32 + (lane >> 4) * 16);
                LDSM4(a[mi], ad);
            }
#pragma unroll
            for (int pr = 0; pr < 2; pr++) {
                uint32_t t4[4];
                uint32_t bd = sB + (uint32_t)((wn * 32 + pr * 16 + ((lane >> 4) & 1) * 8
                                               + (lane & 7)) * 80
                                              + kk * 32 + ((lane >> 3) & 1) * 16);
                LDSM4(t4, bd);
                b[2 * pr][0] = t4[0]; b[2 * pr][1] = t4[1];
                b[2 * pr + 1][0] = t4[2]; b[2 * pr + 1][1] = t4[3];
            }
#pragma unroll
            for (int mi = 0; mi < 4; mi++)
#pragma unroll
                for (int ni = 0; ni < 4; ni++)
                    MMA_BF16(acc[mi][ni], a[mi], b[ni]);
        }
    }

#pragma unroll
    for (int mi = 0; mi < 4; mi++)
#pragma unroll
        for (int ni = 0; ni < 4; ni++) {
            int row = m0 + wm * 64 + mi * 16 + (lane >> 2);
            int col = n0 + wn * 32 + ni * 8 + (lane & 3) * 2;
            float b0 = 0.f, b1 = 0.f;
            if (HAS_BIAS) { b0 = bias[col]; b1 = bias[col + 1]; }
            float2 v0 = { acc[mi][ni][0] + b0, acc[mi][ni][1] + b1 };
            float2 v1 = { acc[mi][ni][2] + b0, acc[mi][ni][3] + b1 };
            *(float2*)&C[(size_t)row * Ncols + col] = v0;
            *(float2*)&C[(size_t)(row + 8) * Ncols + col] = v1;
        }
#undef G_LOAD
}

// ---------------- HMMA flash attention --------------------------------------
// Br=128 (4 warps x 32 rows), Bc=64, hd=64. smem stride 72 bf16.
// offsets (elems): Qh 0, Ql 9216, Kh 18432, Kl 23040, Vh 27648, Vl 32256
#define FQ  9216
#define FKV 4608
#define FA_SMEM_B (36864 * 2)

__global__ __launch_bounds__(128)
void flash_mma() {
    extern __shared__ __nv_bfloat16 fsm[];
    const uint32_t sbase = smem_u32(fsm);
    const uint32_t sQh = sbase, sQl = sbase + FQ * 2;
    const uint32_t sKh = sbase + 2 * FQ * 2,        sKl = sKh + FKV * 2;
    const uint32_t sVh = sKl + FKV * 2,             sVl = sVh + FKV * 2;

    const int tid = threadIdx.x, lane = tid & 31, wid = tid >> 5;
    const int b = blockIdx.y >> 4, h = blockIdx.y & 15;
    const int q0 = blockIdx.x * 128;
    const int wq = wid * 32;
    const size_t base = ((size_t)b * NT) * ND + (size_t)h * NHD;

    // Q load (hi+lo)
    {
        const __nv_bfloat16* qs[2] = { g_Qh + base, g_Ql + base };
#pragma unroll
        for (int i = 0; i < 16; i++) {
            int idx = i * 128 + tid;
            int arr = idx >> 10, rem = idx & 1023;
            int r = rem >> 3, sg = rem & 7;
            CPA16((arr ? sQl : sQh) + (uint32_t)(r * 144 + sg * 16),
                  qs[arr] + (size_t)(q0 + r) * ND + sg * 8);
        }
    }
    // KV tile 0
    {
        const __nv_bfloat16* gs[4] = { g_Kh + base, g_Kl + base, g_Vh + base, g_Vl + base };
        const uint32_t sd[4] = { sKh, sKl, sVh, sVl };
#pragma unroll
        for (int i = 0; i < 16; i++) {
            int idx = i * 128 + tid;
            int arr = idx >> 9, rem = idx & 511;
            int r = rem >> 3, sg = rem & 7;
            CPA16(sd[arr] + (uint32_t)(r * 144 + sg * 16),
                  gs[arr] + (size_t)r * ND + sg * 8);
        }
    }
    CPCOMMIT(); CPWAIT0(); __syncthreads();

    float o[2][8][4];
    float mrow[2][2], lrow[2][2];
#pragma unroll
    for (int mi = 0; mi < 2; mi++) {
        mrow[mi][0] = mrow[mi][1] = -1e30f;
        lrow[mi][0] = lrow[mi][1] = 0.f;
#pragma unroll
        for (int nd = 0; nd < 8; nd++)
#pragma unroll
            for (int k = 0; k < 4; k++) o[mi][nd][k] = 0.f;
    }

    for (int t = 0; t < NT / 64; t++) {
        // ---- S = Q K^T (3 split terms) ----
        float s[2][8][4];
#pragma unroll
        for (int mi = 0; mi < 2; mi++)
#pragma unroll
            for (int ni = 0; ni < 8; ni++)
#pragma unroll
                for (int k = 0; k < 4; k++) s[mi][ni][k] = 0.f;

#pragma unroll
        for (int kk = 0; kk < 4; kk++) {
            uint32_t aqh[2][4], aql[2][4];
#pragma unroll
            for (int mi = 0; mi < 2; mi++) {
                uint32_t off = (uint32_t)((wq + mi * 16 + (lane & 15)) * 144
                                          + kk * 32 + (lane >> 4) * 16);
                LDSM4(aqh[mi], sQh + off);
                LDSM4(aql[mi], sQl + off);
            }
            uint32_t bkh[8][2], bkl[8][2];
#pragma unroll
            for (int pr = 0; pr < 4; pr++) {
                uint32_t off = (uint32_t)((pr * 16 + ((lane >> 4) & 1) * 8 + (lane & 7)) * 144
                                          + kk * 32 + ((lane >> 3) & 1) * 16);
                uint32_t t4[4];
                LDSM4(t4, sKh + off);
                bkh[2 * pr][0] = t4[0]; bkh[2 * pr][1] = t4[1];
                bkh[2 * pr + 1][0] = t4[2]; bkh[2 * pr + 1][1] = t4[3];
                LDSM4(t4, sKl + off);
                bkl[2 * pr][0] = t4[0]; bkl[2 * pr][1] = t4[1];
                bkl[2 * pr + 1][0] = t4[2]; bkl[2 * pr + 1][1] = t4[3];
            }
#pragma unroll
            for (int mi = 0; mi < 2; mi++)
#pragma unroll
                for (int ni = 0; ni < 8; ni++) {
                    MMA_BF16(s[mi][ni], aqh[mi], bkh[ni]);
                    MMA_BF16(s[mi][ni], aqh[mi], bkl[ni]);
                    MMA_BF16(s[mi][ni], aql[mi], bkh[ni]);
                }
        }

        // ---- online softmax (exp2 domain; scale folded into Q) ----
#pragma unroll
        for (int mi = 0; mi < 2; mi++)
#pragma unroll
            for (int hf = 0; hf < 2; hf++) {
                float vmax = -1e30f;
#pragma unroll
                for (int ni = 0; ni < 8; ni++)
                    vmax = fmaxf(vmax, fmaxf(s[mi][ni][2 * hf], s[mi][ni][2 * hf + 1]));
                vmax = fmaxf(vmax, __shfl_xor_sync(0xffffffffu, vmax, 1));
                vmax = fmaxf(vmax, __shfl_xor_sync(0xffffffffu, vmax, 2));
                float mo = mrow[mi][hf];
                float mn = fmaxf(mo, vmax);
                float corr = exp2f(mo - mn);
                mrow[mi][hf] = mn;
                float rs = 0.f;
#pragma unroll
                for (int ni = 0; ni < 8; ni++) {
                    float p0 = exp2f(s[mi][ni][2 * hf] - mn);
                    float p1 = exp2f(s[mi][ni][2 * hf + 1] - mn);
                    s[mi][ni][2 * hf] = p0;
                    s[mi][ni][2 * hf + 1] = p1;
                    rs += p0 + p1;
                }
                rs += __shfl_xor_sync(0xffffffffu, rs, 1);
                rs += __shfl_xor_sync(0xffffffffu, rs, 2);
                lrow[mi][hf] = lrow[mi][hf] * corr + rs;
#pragma unroll
                for (int ni = 0; ni < 8; ni++) {
                    o[mi][ni][2 * hf] *= corr;
                    o[mi][ni][2 * hf + 1] *= corr;
                }
            }

        // ---- O += P V (3 split terms) ----
#pragma unroll
        for (int kk = 0; kk < 4; kk++) {
            uint32_t bvh[8][2], bvl[8][2];
#pragma unroll
            for (int q = 0; q < 4; q++) {
                uint32_t off = (uint32_t)((kk * 16 + ((lane >> 3) & 1) * 8 + (lane & 7)) * 144
                                          + q * 32 + ((lane >> 4) & 1) * 16);
                uint32_t t4[4];
                LDSM4T(t4, sVh + off);
                bvh[2 * q][0] = t4[0]; bvh[2 * q][1] = t4[1];
                bvh[2 * q + 1][0] = t4[2]; bvh[2 * q + 1][1] = t4[3];
                LDSM4T(t4, sVl + off);
                bvl[2 * q][0] = t4[0]; bvl[2 * q][1] = t4[1];
                bvl[2 * q + 1][0] = t4[2]; bvl[2 * q + 1][1] = t4[3];
            }
#pragma unroll
            for (int mi = 0; mi < 2; mi++) {
                const float* p0 = s[mi][2 * kk];
                const float* p1 = s[mi][2 * kk + 1];
                float h00 = __bfloat162float(__float2bfloat16(p0[0]));
                float h01 = __bfloat162float(__float2bfloat16(p0[1]));
                float h02 = __bfloat162float(__float2bfloat16(p0[2]));
                float h03 = __bfloat162float(__float2bfloat16(p0[3]));
                float h10 = __bfloat162float(__float2bfloat16(p1[0]));
                float h11 = __bfloat162float(__float2bfloat16(p1[1]));
                float h12 = __bfloat162float(__float2bfloat16(p1[2]));
                float h13 = __bfloat162float(__float2bfloat16(p1[3]));
                uint32_t ah[4], al[4];
                ah[0] = pack_bf16(h00, h01); ah[1] = pack_bf16(h02, h03);
                ah[2] = pack_bf16(h10, h11); ah[3] = pack_bf16(h12, h13);
                al[0] = pack_bf16(p0[0] - h00, p0[1] - h01);
                al[1] = pack_bf16(p0[2] - h02, p0[3] - h03);
                al[2] = pack_bf16(p1[0] - h10, p1[1] - h11);
                al[3] = pack_bf16(p1[2] - h12, p1[3] - h13);
#pragma unroll
                for (int nd = 0; nd < 8; nd++) {
                    MMA_BF16(o[mi][nd], ah, bvh[nd]);
                    MMA_BF16(o[mi][nd], al, bvh[nd]);
                    MMA_BF16(o[mi][nd], ah, bvl[nd]);
                }
            }
        }

        // ---- next KV tile ----
        if (t < NT / 64 - 1) {
            __syncthreads();
            const __nv_bfloat16* gs[4] = { g_Kh + base, g_Kl + base, g_Vh + base, g_Vl + base };
            const uint32_t sd[4] = { sKh, sKl, sVh, sVl };
            int kv0 = (t + 1) * 64;
#pragma unroll
            for (int i = 0; i < 16; i++) {
                int idx = i * 128 + tid;
                int arr = idx >> 9, rem = idx & 511;
                int r = rem >> 3, sg = rem & 7;
                CPA16(sd[arr] + (uint32_t)(r * 144 + sg * 16),
                      gs[arr] + (size_t)(kv0 + r) * ND + sg * 8);
            }
            CPCOMMIT(); CPWAIT0(); __syncthreads();
        }
    }

    // ---- epilogue ----
#pragma unroll
    for (int mi = 0; mi < 2; mi++)
#pragma unroll
        for (int hf = 0; hf < 2; hf++) {
            float inv = 1.f / lrow[mi][hf];
            int row = q0 + wq + mi * 16 + (lane >> 2) + hf * 8;
#pragma unroll
            for (int nd = 0; nd < 8; nd++) {
                int col = h * 64 + nd * 8 + (lane & 3) * 2;
                float2 v = { o[mi][nd][2 * hf] * inv, o[mi][nd][2 * hf + 1] * inv };
                *(float2*)&g_O[((size_t)b * NT + row) * ND + col] = v;
            }
        }
}

// ---------------- host launcher --------------------------------------------
extern "C" void kernel_launch(void* const* d_in, const int* in_sizes, int n_in,
                              void* d_out, int out_size) {
    (void)in_sizes; (void)n_in; (void)out_size;
    const float* x  = (const float*)d_in[0];
    const float* Wq = (const float*)d_in[1];
    const float* Wk = (const float*)d_in[2];
    const float* Wv = (const float*)d_in[3];
    const float* Wo = (const float*)d_in[4];
    const float* bo = (const float*)d_in[5];
    float* out = (float*)d_out;

    float *QKVp, *Op, *Wvpp;
    __nv_bfloat16 *A2p, *W2p, *Wo2p;
    cudaGetSymbolAddress((void**)&QKVp, g_QKV);
    cudaGetSymbolAddress((void**)&Op, g_O);
    cudaGetSymbolAddress((void**)&Wvpp, g_Wvp);
    cudaGetSymbolAddress((void**)&A2p, g_A2);
    cudaGetSymbolAddress((void**)&W2p, g_W2);
    cudaGetSymbolAddress((void**)&Wo2p, g_Wo2);

    rope_build<<<(NT * NHD + 255) / 256, 256>>>();
    compute_R<<<(NHD * NHD) / 256, 256>>>();
    fold_wv<<<(ND * ND) / 256, 256>>>(Wv);

    prep_a<<<(NBT * ND) / 256, 256>>>(x, A2p, NBT * ND);
    dim3 pwg(32, 32), pwb(32, 8);
    prep_w<<<pwg, pwb>>>(Wq, W2p);
    prep_w<<<pwg, pwb>>>(Wk, W2p + (size_t)1024 * GK);
    prep_w<<<pwg, pwb>>>(Wvpp, W2p + (size_t)2048 * GK);
    prep_w<<<pwg, pwb>>>(Wo, Wo2p);

    cudaFuncSetAttribute(gemm_mma<false>, cudaFuncAttributeMaxDynamicSharedMemorySize, GSMEM_B);
    cudaFuncSetAttribute(gemm_mma<true>,  cudaFuncAttributeMaxDynamicSharedMemorySize, GSMEM_B);
    gemm_mma<false><<<dim3(QKV_LD / 128, NBT / 128), 256, GSMEM_B>>>(A2p, W2p, QKVp, nullptr, QKV_LD);

    qkv_split<<<(NBT * ND) / 256, 256>>>();

    cudaFuncSetAttribute(flash_mma, cudaFuncAttributeMaxDynamicSharedMemorySize, FA_SMEM_B);
    flash_mma<<<dim3(NT / 128, NB * NH), 128, FA_SMEM_B>>>();

    prep_a<<<(NBT * ND) / 256, 256>>>(Op, A2p, NBT * ND);
    gemm_mma<true><<<dim3(ND / 128, NBT / 128), 256, GSMEM_B>>>(A2p, Wo2p, out, bo, ND);
}

// round 5
// speedup vs baseline: 2.5299x; 1.0491x over previous
#include <cuda_runtime.h>
#include <cuda_bf16.h>
#include <cstdint>
#include <math.h>

#define NB 2
#define NT 2048
#define ND 1024
#define NH 16
#define NHD 64
#define NBT (NB*NT)
#define GK 3072            // split-bf16 stacked K
#define NCHUNK (GK/32)     // 96 chunks of BK=32
#define QSCALE 0.18033688011111772f   // 0.125 * log2(e)

// ---------------- scratch ---------------------------------------------------
__device__ __nv_bfloat16 g_A2[(size_t)NBT*GK];
__device__ __nv_bfloat16 g_W2[(size_t)GK*GK];        // [n,k] split Wq|Wk|Wv'
__device__ __nv_bfloat16 g_Wo2[(size_t)ND*GK];
__device__ float g_rope[(size_t)NT*NHD];
__device__ float g_R[NHD*NHD];
__device__ float g_Wvp[(size_t)ND*ND];
__device__ __nv_bfloat16 g_Qh[(size_t)NBT*ND], g_Ql[(size_t)NBT*ND];
__device__ __nv_bfloat16 g_Kh[(size_t)NBT*ND], g_Kl[(size_t)NBT*ND];
__device__ __nv_bfloat16 g_Vh[(size_t)NBT*ND], g_Vl[(size_t)NBT*ND];

// ---------------- helpers ---------------------------------------------------
__device__ __forceinline__ uint32_t smem_u32(const void* p) {
    uint32_t a;
    asm("{ .reg .u64 t; cvta.to.shared.u64 t, %1; cvt.u32.u64 %0, t; }"
        : "=r"(a) : "l"(p));
    return a;
}
#define CPA16(s, g) asm volatile("cp.async.cg.shared.global [%0], [%1], 16;\n" :: "r"(s), "l"(g))
#define CPCOMMIT()  asm volatile("cp.async.commit_group;\n" ::: "memory")
#define CPWAIT0()   asm volatile("cp.async.wait_group 0;\n" ::: "memory")
#define CPWAIT1()   asm volatile("cp.async.wait_group 1;\n" ::: "memory")

#define LDSM4(r, addr)                                                        \
    asm volatile("ldmatrix.sync.aligned.m8n8.x4.shared.b16 {%0,%1,%2,%3}, [%4];" \
                 : "=r"((r)[0]), "=r"((r)[1]), "=r"((r)[2]), "=r"((r)[3])     \
                 : "r"(addr))
#define LDSM4T(r, addr)                                                       \
    asm volatile("ldmatrix.sync.aligned.m8n8.x4.trans.shared.b16 {%0,%1,%2,%3}, [%4];" \
                 : "=r"((r)[0]), "=r"((r)[1]), "=r"((r)[2]), "=r"((r)[3])     \
                 : "r"(addr))
#define MMA_BF16(d, a, b)                                                     \
    asm volatile("mma.sync.aligned.m16n8k16.row.col.f32.bf16.bf16.f32 "       \
                 "{%0,%1,%2,%3},{%4,%5,%6,%7},{%8,%9},{%0,%1,%2,%3};"         \
                 : "+f"((d)[0]), "+f"((d)[1]), "+f"((d)[2]), "+f"((d)[3])     \
                 : "r"((a)[0]), "r"((a)[1]), "r"((a)[2]), "r"((a)[3]),        \
                   "r"((b)[0]), "r"((b)[1]))

// packs (lo_val -> lower half, hi_val -> upper half)
__device__ __forceinline__ uint32_t pack_bf16(float lo, float hi) {
    uint32_t r;
    asm("cvt.rn.bf16x2.f32 %0, %1, %2;" : "=r"(r) : "f"(hi), "f"(lo));
    return r;
}
// split a pair of f32 (a0 -> lower, a1 -> upper) into hi-pair and lo-pair
__device__ __forceinline__ void split_pair(float a0, float a1, uint32_t& hp, uint32_t& lp) {
    hp = pack_bf16(a0, a1);
    float h0 = __uint_as_float(hp << 16);
    float h1 = __uint_as_float(hp & 0xFFFF0000u);
    lp = pack_bf16(a0 - h0, a1 - h1);
}

// ---------------- rope / R / fold -------------------------------------------
__global__ void rope_build() {
    int g = blockIdx.x * blockDim.x + threadIdx.x;
    if (g >= NT * NHD) return;
    int s = g >> 6, i = g & 63, k = i & 31;
    double inv = exp(-(double)k * (log(10000.0) / 32.0));
    double ph = (double)s * inv;
    g_rope[g] = (i < 32) ? (float)cos(ph) : (float)sin(ph);
}
__global__ void compute_R() {
    int g = blockIdx.x * blockDim.x + threadIdx.x;
    int i = g >> 6, j = g & 63;
    float acc = 0.f;
    for (int s = 0; s < NT; s++)
        acc += g_rope[s * 64 + i] * g_rope[s * 64 + j];
    g_R[i * 64 + j] = acc;
}
__global__ void fold_wv(const float* __restrict__ Wv) {
    int g = blockIdx.x * blockDim.x + threadIdx.x;
    int j = g & 63;
    int h = (g >> 6) & (NH - 1);
    int d = g >> 10;
    const float* wrow = Wv + (size_t)d * ND + h * 64;
    float acc = 0.f;
#pragma unroll 8
    for (int i = 0; i < 64; i++)
        acc += wrow[i] * g_R[i * 64 + j];
    g_Wvp[g] = acc;
}

// ---------------- split preparation -----------------------------------------
__global__ void prep_a(const float* __restrict__ X, __nv_bfloat16* __restrict__ A2, int Melems) {
    int g = blockIdx.x * blockDim.x + threadIdx.x;
    if (g >= Melems) return;
    int m = g >> 10, k = g & 1023;
    float v = X[g];
    __nv_bfloat16 hi = __float2bfloat16(v);
    __nv_bfloat16 lo = __float2bfloat16(v - __bfloat162float(hi));
    size_t base = (size_t)m * GK;
    A2[base + k] = hi;
    A2[base + 1024 + k] = lo;
    A2[base + 2048 + k] = hi;
}
__global__ void prep_w(const float* __restrict__ W, __nv_bfloat16* __restrict__ W2) {
    __shared__ float t[32][33];
    int k0 = blockIdx.y * 32, n0 = blockIdx.x * 32;
    int tx = threadIdx.x, ty = threadIdx.y;
#pragma unroll
    for (int i = 0; i < 32; i += 8)
        t[ty + i][tx] = W[(size_t)(k0 + ty + i) * ND + n0 + tx];
    __syncthreads();
#pragma unroll
    for (int i = 0; i < 32; i += 8) {
        int n = n0 + ty + i, k = k0 + tx;
        float v = t[tx][ty + i];
        __nv_bfloat16 hi = __float2bfloat16(v);
        __nv_bfloat16 lo = __float2bfloat16(v - __bfloat162float(hi));
        size_t b = (size_t)n * GK;
        W2[b + k] = hi;
        W2[b + 1024 + k] = hi;
        W2[b + 2048 + k] = lo;
    }
}

// ---------------- HMMA GEMM: 128x128x32 tile, 4 warps (2x2 of 64x64) --------
// EPI: 0 = f32 store, 1 = f32 store + bias, 2 = QKV hi/lo split store
#define GST 10240                      // bytes per stage per operand (128*40*2)
#define GSMEM_B (6 * GST)              // 61440 bytes

template<int EPI>
__global__ __launch_bounds__(128)
void gemm_mma(const __nv_bfloat16* __restrict__ A, const __nv_bfloat16* __restrict__ B,
              float* __restrict__ C, const float* __restrict__ bias, int Ncols)
{
    extern __shared__ __nv_bfloat16 gsm[];
    const uint32_t sbase = smem_u32(gsm);
    const int tid = threadIdx.x, lane = tid & 31, wid = tid >> 5;
    const int wm = wid >> 1, wn = wid & 1;
    const int m0 = blockIdx.y * 128, n0 = blockIdx.x * 128;
    const __nv_bfloat16* Ap = A + (size_t)m0 * GK;
    const __nv_bfloat16* Bp = B + (size_t)n0 * GK;

#define G_LOAD(st, ch)                                                        \
    do {                                                                      \
        uint32_t _sA = sbase + (st) * GST;                                    \
        uint32_t _sB = sbase + 3 * GST + (st) * GST;                          \
        const __nv_bfloat16* _ag = Ap + (ch) * 32;                            \
        const __nv_bfloat16* _bg = Bp + (ch) * 32;                            \
        _Pragma("unroll")                                                     \
        for (int _i = 0; _i < 4; _i++) {                                      \
            int _idx = _i * 128 + tid;                                        \
            int _r = _idx >> 2, _sg = _idx & 3;                               \
            uint32_t _o = (uint32_t)(_r * 80 + _sg * 16);                     \
            CPA16(_sA + _o, _ag + (size_t)_r * GK + _sg * 8);                 \
            CPA16(_sB + _o, _bg + (size_t)_r * GK + _sg * 8);                 \
        }                                                                     \
        CPCOMMIT();                                                           \
    } while (0)

    float acc[4][8][4];
#pragma unroll
    for (int i = 0; i < 4; i++)
#pragma unroll
        for (int j = 0; j < 8; j++)
#pragma unroll
            for (int k = 0; k < 4; k++) acc[i][j][k] = 0.f;

    G_LOAD(0, 0);
    G_LOAD(1, 1);

    for (int c = 0; c < NCHUNK; c++) {
        if (c < NCHUNK - 1) CPWAIT1(); else CPWAIT0();
        __syncthreads();
        if (c + 2 < NCHUNK) G_LOAD((c + 2) % 3, c + 2);

        int st = c % 3;
        uint32_t sA = sbase + st * GST;
        uint32_t sB = sbase + 3 * GST + st * GST;
#pragma unroll
        for (int kk = 0; kk < 2; kk++) {
            uint32_t a[4][4], b[8][2];
#pragma unroll
            for (int mi = 0; mi < 4; mi++) {
                uint32_t ad = sA + (uint32_t)((wm * 64 + mi * 16 + (lane & 15)) * 80
                                              + kk * 32 + (lane >> 4) * 16);
                LDSM4(a[mi], ad);
            }
#pragma unroll
            for (int pr = 0; pr < 4; pr++) {
                uint32_t t4[4];
                uint32_t bd = sB + (uint32_t)((wn * 64 + pr * 16 + ((lane >> 4) & 1) * 8
                                               + (lane & 7)) * 80
                                              + kk * 32 + ((lane >> 3) & 1) * 16);
                LDSM4(t4, bd);
                b[2 * pr][0] = t4[0]; b[2 * pr][1] = t4[1];
                b[2 * pr + 1][0] = t4[2]; b[2 * pr + 1][1] = t4[3];
            }
#pragma unroll
            for (int mi = 0; mi < 4; mi++)
#pragma unroll
                for (int ni = 0; ni < 8; ni++)
                    MMA_BF16(acc[mi][ni], a[mi], b[ni]);
        }
    }

    if (EPI == 2) {
        // write Q/K/V hi/lo split directly; arr uniform per CTA
        const int arr = n0 >> 10;
        __nv_bfloat16* hb = (arr == 0) ? g_Qh : (arr == 1) ? g_Kh : g_Vh;
        __nv_bfloat16* lb = (arr == 0) ? g_Ql : (arr == 1) ? g_Kl : g_Vl;
        const float sc = (arr == 0) ? QSCALE : 1.f;
#pragma unroll
        for (int mi = 0; mi < 4; mi++)
#pragma unroll
            for (int ni = 0; ni < 8; ni++) {
                int row = m0 + wm * 64 + mi * 16 + (lane >> 2);
                int c = (n0 & 1023) + wn * 64 + ni * 8 + (lane & 3) * 2;
                uint32_t hp, lp;
                split_pair(acc[mi][ni][0] * sc, acc[mi][ni][1] * sc, hp, lp);
                size_t di = (size_t)row * ND + c;
                *(uint32_t*)&hb[di] = hp;
                *(uint32_t*)&lb[di] = lp;
                split_pair(acc[mi][ni][2] * sc, acc[mi][ni][3] * sc, hp, lp);
                di += (size_t)8 * ND;
                *(uint32_t*)&hb[di] = hp;
                *(uint32_t*)&lb[di] = lp;
            }
    } else {
#pragma unroll
        for (int mi = 0; mi < 4; mi++)
#pragma unroll
            for (int ni = 0; ni < 8; ni++) {
                int row = m0 + wm * 64 + mi * 16 + (lane >> 2);
                int col = n0 + wn * 64 + ni * 8 + (lane & 3) * 2;
                float b0 = 0.f, b1 = 0.f;
                if (EPI == 1) { b0 = bias[col]; b1 = bias[col + 1]; }
                float2 v0 = { acc[mi][ni][0] + b0, acc[mi][ni][1] + b1 };
                float2 v1 = { acc[mi][ni][2] + b0, acc[mi][ni][3] + b1 };
                *(float2*)&C[(size_t)row * Ncols + col] = v0;
                *(float2*)&C[(size_t)(row + 8) * Ncols + col] = v1;
            }
    }
#undef G_LOAD
}

// ---------------- HMMA flash attention --------------------------------------
// Br=128 (4 warps x 32 rows), Bc=64, hd=64, double-buffered KV.
// smem elems: Qh 9216, Ql 9216, then 2 stages x {Kh,Kl,Vh,Vl} x 4608
#define FQ  9216
#define FKV 4608
#define FA_SMEM_B ((2 * FQ + 2 * 4 * FKV) * 2)   // 110592 bytes

__global__ __launch_bounds__(128)
void flash_mma() {
    extern __shared__ __nv_bfloat16 fsm[];
    const uint32_t sbase = smem_u32(fsm);
    const uint32_t sQh = sbase, sQl = sbase + FQ * 2;
    const uint32_t sKV0 = sbase + 2 * FQ * 2;

    const int tid = threadIdx.x, lane = tid & 31, wid = tid >> 5;
    const int b = blockIdx.y >> 4, h = blockIdx.y & 15;
    const int q0 = blockIdx.x * 128;
    const int wq = wid * 32;
    const size_t base = ((size_t)b * NT) * ND + (size_t)h * NHD;

    const __nv_bfloat16* gs[4] = { g_Kh + base, g_Kl + base, g_Vh + base, g_Vl + base };

#define KV_LOAD(stg, kv0)                                                     \
    do {                                                                      \
        uint32_t _sd = sKV0 + (stg) * (4 * FKV * 2);                          \
        _Pragma("unroll")                                                     \
        for (int _i = 0; _i < 16; _i++) {                                     \
            int _idx = _i * 128 + tid;                                        \
            int _arr = _idx >> 9, _rem = _idx & 511;                          \
            int _r = _rem >> 3, _sg = _rem & 7;                               \
            CPA16(_sd + (uint32_t)(_arr * (FKV * 2) + _r * 144 + _sg * 16),   \
                  gs[_arr] + (size_t)((kv0) + _r) * ND + _sg * 8);            \
        }                                                                     \
        CPCOMMIT();                                                           \
    } while (0)

    // Q load (hi+lo) — same commit group as KV tile 0
    {
        const __nv_bfloat16* qs[2] = { g_Qh + base, g_Ql + base };
#pragma unroll
        for (int i = 0; i < 16; i++) {
            int idx = i * 128 + tid;
            int arr = idx >> 10, rem = idx & 1023;
            int r = rem >> 3, sg = rem & 7;
            CPA16((arr ? sQl : sQh) + (uint32_t)(r * 144 + sg * 16),
                  qs[arr] + (size_t)(q0 + r) * ND + sg * 8);
        }
    }
    KV_LOAD(0, 0);
    KV_LOAD(1, 64);

    float o[2][8][4];
    float mrow[2][2], lrow[2][2];
#pragma unroll
    for (int mi = 0; mi < 2; mi++) {
        mrow[mi][0] = mrow[mi][1] = -1e30f;
        lrow[mi][0] = lrow[mi][1] = 0.f;
#pragma unroll
        for (int nd = 0; nd < 8; nd++)
#pragma unroll
            for (int k = 0; k < 4; k++) o[mi][nd][k] = 0.f;
    }

    for (int t = 0; t < NT / 64; t++) {
        if (t < NT / 64 - 1) CPWAIT1(); else CPWAIT0();
        __syncthreads();
        const uint32_t sKh = sKV0 + (t & 1) * (4 * FKV * 2);
        const uint32_t sKl = sKh + FKV * 2;
        const uint32_t sVh = sKl + FKV * 2;
        const uint32_t sVl = sVh + FKV * 2;

        // ---- S = Q K^T (3 split terms) ----
        float s[2][8][4];
#pragma unroll
        for (int mi = 0; mi < 2; mi++)
#pragma unroll
            for (int ni = 0; ni < 8; ni++)
#pragma unroll
                for (int k = 0; k < 4; k++) s[mi][ni][k] = 0.f;

#pragma unroll
        for (int kk = 0; kk < 4; kk++) {
            uint32_t aqh[2][4], aql[2][4];
#pragma unroll
            for (int mi = 0; mi < 2; mi++) {
                uint32_t off = (uint32_t)((wq + mi * 16 + (lane & 15)) * 144
                                          + kk * 32 + (lane >> 4) * 16);
                LDSM4(aqh[mi], sQh + off);
                LDSM4(aql[mi], sQl + off);
            }
            uint32_t bkh[8][2], bkl[8][2];
#pragma unroll
            for (int pr = 0; pr < 4; pr++) {
                uint32_t off = (uint32_t)((pr * 16 + ((lane >> 4) & 1) * 8 + (lane & 7)) * 144
                                          + kk * 32 + ((lane >> 3) & 1) * 16);
                uint32_t t4[4];
                LDSM4(t4, sKh + off);
                bkh[2 * pr][0] = t4[0]; bkh[2 * pr][1] = t4[1];
                bkh[2 * pr + 1][0] = t4[2]; bkh[2 * pr + 1][1] = t4[3];
                LDSM4(t4, sKl + off);
                bkl[2 * pr][0] = t4[0]; bkl[2 * pr][1] = t4[1];
                bkl[2 * pr + 1][0] = t4[2]; bkl[2 * pr + 1][1] = t4[3];
            }
#pragma unroll
            for (int mi = 0; mi < 2; mi++)
#pragma unroll
                for (int ni = 0; ni < 8; ni++) {
                    MMA_BF16(s[mi][ni], aqh[mi], bkh[ni]);
                    MMA_BF16(s[mi][ni], aqh[mi], bkl[ni]);
                    MMA_BF16(s[mi][ni], aql[mi], bkh[ni]);
                }
        }

        // ---- online softmax (exp2 domain; scale folded into Q) ----
#pragma unroll
        for (int mi = 0; mi < 2; mi++)
#pragma unroll
            for (int hf = 0; hf < 2; hf++) {
                float vmax = -1e30f;
#pragma unroll
                for (int ni = 0; ni < 8; ni++)
                    vmax = fmaxf(vmax, fmaxf(s[mi][ni][2 * hf], s[mi][ni][2 * hf + 1]));
                vmax = fmaxf(vmax, __shfl_xor_sync(0xffffffffu, vmax, 1));
                vmax = fmaxf(vmax, __shfl_xor_sync(0xffffffffu, vmax, 2));
                float mo = mrow[mi][hf];
                float mn = fmaxf(mo, vmax);
                float corr = exp2f(mo - mn);
                mrow[mi][hf] = mn;
                float rs = 0.f;
#pragma unroll
                for (int ni = 0; ni < 8; ni++) {
                    float p0 = exp2f(s[mi][ni][2 * hf] - mn);
                    float p1 = exp2f(s[mi][ni][2 * hf + 1] - mn);
                    s[mi][ni][2 * hf] = p0;
                    s[mi][ni][2 * hf + 1] = p1;
                    rs += p0 + p1;
                }
                rs += __shfl_xor_sync(0xffffffffu, rs, 1);
                rs += __shfl_xor_sync(0xffffffffu, rs, 2);
                lrow[mi][hf] = lrow[mi][hf] * corr + rs;
#pragma unroll
                for (int ni = 0; ni < 8; ni++) {
                    o[mi][ni][2 * hf] *= corr;
                    o[mi][ni][2 * hf + 1] *= corr;
                }
            }

        // ---- O += P V (3 split terms) ----
#pragma unroll
        for (int kk = 0; kk < 4; kk++) {
            uint32_t bvh[8][2], bvl[8][2];
#pragma unroll
            for (int q = 0; q < 4; q++) {
                uint32_t off = (uint32_t)((kk * 16 + ((lane >> 3) & 1) * 8 + (lane & 7)) * 144
                                          + q * 32 + ((lane >> 4) & 1) * 16);
                uint32_t t4[4];
                LDSM4T(t4, sVh + off);
                bvh[2 * q][0] = t4[0]; bvh[2 * q][1] = t4[1];
                bvh[2 * q + 1][0] = t4[2]; bvh[2 * q + 1][1] = t4[3];
                LDSM4T(t4, sVl + off);
                bvl[2 * q][0] = t4[0]; bvl[2 * q][1] = t4[1];
                bvl[2 * q + 1][0] = t4[2]; bvl[2 * q + 1][1] = t4[3];
            }
#pragma unroll
            for (int mi = 0; mi < 2; mi++) {
                const float* p0 = s[mi][2 * kk];
                const float* p1 = s[mi][2 * kk + 1];
                uint32_t ah[4], al[4];
                {
                    uint32_t hp, lp;
                    split_pair(p0[0], p0[1], hp, lp); ah[0] = hp; al[0] = lp;
                    split_pair(p0[2], p0[3], hp, lp); ah[1] = hp; al[1] = lp;
                    split_pair(p1[0], p1[1], hp, lp); ah[2] = hp; al[2] = lp;
                    split_pair(p1[2], p1[3], hp, lp); ah[3] = hp; al[3] = lp;
                }
#pragma unroll
                for (int nd = 0; nd < 8; nd++) {
                    MMA_BF16(o[mi][nd], ah, bvh[nd]);
                    MMA_BF16(o[mi][nd], al, bvh[nd]);
                    MMA_BF16(o[mi][nd], ah, bvl[nd]);
                }
            }
        }

        // ---- prefetch KV tile t+2 into the buffer we just consumed ----
        if (t + 2 < NT / 64) {
            __syncthreads();
            KV_LOAD(t & 1, (t + 2) * 64);
        }
    }

    // ---- epilogue: write hi/lo A2 layout directly ----
#pragma unroll
    for (int mi = 0; mi < 2; mi++)
#pragma unroll
        for (int hf = 0; hf < 2; hf++) {
            float inv = 1.f / lrow[mi][hf];
            int m = b * NT + q0 + wq + mi * 16 + (lane >> 2) + hf * 8;
#pragma unroll
            for (int nd = 0; nd < 8; nd++) {
                int k = h * 64 + nd * 8 + (lane & 3) * 2;
                float a0 = o[mi][nd][2 * hf] * inv;
                float a1 = o[mi][nd][2 * hf + 1] * inv;
                uint32_t hp, lp;
                split_pair(a0, a1, hp, lp);
                size_t di = (size_t)m * GK + k;
                *(uint32_t*)&g_A2[di] = hp;
                *(uint32_t*)&g_A2[di + 1024] = lp;
                *(uint32_t*)&g_A2[di + 2048] = hp;
            }
        }
#undef KV_LOAD
}

// ---------------- host launcher --------------------------------------------
extern "C" void kernel_launch(void* const* d_in, const int* in_sizes, int n_in,
                              void* d_out, int out_size) {
    (void)in_sizes; (void)n_in; (void)out_size;
    const float* x  = (const float*)d_in[0];
    const float* Wq = (const float*)d_in[1];
    const float* Wk = (const float*)d_in[2];
    const float* Wv = (const float*)d_in[3];
    const float* Wo = (const float*)d_in[4];
    const float* bo = (const float*)d_in[5];
    float* out = (float*)d_out;

    float *Wvpp;
    __nv_bfloat16 *A2p, *W2p, *Wo2p;
    cudaGetSymbolAddress((void**)&Wvpp, g_Wvp);
    cudaGetSymbolAddress((void**)&A2p, g_A2);
    cudaGetSymbolAddress((void**)&W2p, g_W2);
    cudaGetSymbolAddress((void**)&Wo2p, g_Wo2);

    rope_build<<<(NT * NHD + 255) / 256, 256>>>();
    compute_R<<<(NHD * NHD) / 256, 256>>>();
    fold_wv<<<(ND * ND) / 256, 256>>>(Wv);

    prep_a<<<(NBT * ND) / 256, 256>>>(x, A2p, NBT * ND);
    dim3 pwg(32, 32), pwb(32, 8);
    prep_w<<<pwg, pwb>>>(Wq, W2p);
    prep_w<<<pwg, pwb>>>(Wk, W2p + (size_t)1024 * GK);
    prep_w<<<pwg, pwb>>>(Wvpp, W2p + (size_t)2048 * GK);
    prep_w<<<pwg, pwb>>>(Wo, Wo2p);

    cudaFuncSetAttribute(gemm_mma<1>, cudaFuncAttributeMaxDynamicSharedMemorySize, GSMEM_B);
    cudaFuncSetAttribute(gemm_mma<2>, cudaFuncAttributeMaxDynamicSharedMemorySize, GSMEM_B);

    // fused QKV projection with split epilogue: [4096,3072]
    gemm_mma<2><<<dim3(3072 / 128, NBT / 128), 128, GSMEM_B>>>(A2p, W2p, nullptr, nullptr, 0);

    cudaFuncSetAttribute(flash_mma, cudaFuncAttributeMaxDynamicSharedMemorySize, FA_SMEM_B);
    flash_mma<<<dim3(NT / 128, NB * NH), 128, FA_SMEM_B>>>();

    // output projection + bias (reads A2 written by flash epilogue)
    gemm_mma<1><<<dim3(ND / 128, NBT / 128), 128, GSMEM_B>>>(A2p, Wo2p, out, bo, ND);
}

// round 6
// speedup vs baseline: 5.3577x; 2.1177x over previous
#include <cuda_runtime.h>
#include <cuda_fp16.h>
#include <cstdint>
#include <math.h>

#define NB 2
#define NT 2048
#define ND 1024
#define NH 16
#define NHD 64
#define NBT (NB*NT)
#define NCHUNK (ND/32)     // 32 chunks of BK=32
#define QSCALE 0.18033688011111772f   // 0.125 * log2(e)

// ---------------- scratch ---------------------------------------------------
__device__ __half g_A[(size_t)NBT*ND];          // fp16 activations (x, later o)
__device__ __half g_W[(size_t)3*ND*ND];         // [n,k] fp16 Wq|Wk|Wv'
__device__ __half g_Wo[(size_t)ND*ND];          // [n,k] fp16 Wo
__device__ float g_rope[(size_t)NT*NHD];
__device__ float g_R[NHD*NHD];
__device__ float g_Wvp[(size_t)ND*ND];
__device__ __half g_Qs[(size_t)NBT*ND];         // q * QSCALE
__device__ __half g_Ks[(size_t)NBT*ND];
__device__ __half g_Vs[(size_t)NBT*ND];

// ---------------- helpers ---------------------------------------------------
__device__ __forceinline__ uint32_t smem_u32(const void* p) {
    uint32_t a;
    asm("{ .reg .u64 t; cvta.to.shared.u64 t, %1; cvt.u32.u64 %0, t; }"
        : "=r"(a) : "l"(p));
    return a;
}
#define CPA16(s, g) asm volatile("cp.async.cg.shared.global [%0], [%1], 16;\n" :: "r"(s), "l"(g))
#define CPCOMMIT()  asm volatile("cp.async.commit_group;\n" ::: "memory")
#define CPWAIT0()   asm volatile("cp.async.wait_group 0;\n" ::: "memory")
#define CPWAIT1()   asm volatile("cp.async.wait_group 1;\n" ::: "memory")

#define LDSM4(r, addr)                                                        \
    asm volatile("ldmatrix.sync.aligned.m8n8.x4.shared.b16 {%0,%1,%2,%3}, [%4];" \
                 : "=r"((r)[0]), "=r"((r)[1]), "=r"((r)[2]), "=r"((r)[3])     \
                 : "r"(addr))
#define LDSM4T(r, addr)                                                       \
    asm volatile("ldmatrix.sync.aligned.m8n8.x4.trans.shared.b16 {%0,%1,%2,%3}, [%4];" \
                 : "=r"((r)[0]), "=r"((r)[1]), "=r"((r)[2]), "=r"((r)[3])     \
                 : "r"(addr))
#define MMA_F16(d, a, b)                                                      \
    asm volatile("mma.sync.aligned.m16n8k16.row.col.f32.f16.f16.f32 "         \
                 "{%0,%1,%2,%3},{%4,%5,%6,%7},{%8,%9},{%0,%1,%2,%3};"         \
                 : "+f"((d)[0]), "+f"((d)[1]), "+f"((d)[2]), "+f"((d)[3])     \
                 : "r"((a)[0]), "r"((a)[1]), "r"((a)[2]), "r"((a)[3]),        \
                   "r"((b)[0]), "r"((b)[1]))

// packs (lo_val -> lower half, hi_val -> upper half)
__device__ __forceinline__ uint32_t pack_f16(float lo, float hi) {
    uint32_t r;
    asm("cvt.rn.f16x2.f32 %0, %1, %2;" : "=r"(r) : "f"(hi), "f"(lo));
    return r;
}

// ---------------- rope / R / fold -------------------------------------------
__global__ void rope_build() {
    int g = blockIdx.x * blockDim.x + threadIdx.x;
    if (g >= NT * NHD) return;
    int s = g >> 6, i = g & 63, k = i & 31;
    double inv = exp(-(double)k * (log(10000.0) / 32.0));
    double ph = (double)s * inv;
    g_rope[g] = (i < 32) ? (float)cos(ph) : (float)sin(ph);
}
__global__ void compute_R() {
    int g = blockIdx.x * blockDim.x + threadIdx.x;
    int i = g >> 6, j = g & 63;
    float acc = 0.f;
    for (int s = 0; s < NT; s++)
        acc += g_rope[s * 64 + i] * g_rope[s * 64 + j];
    g_R[i * 64 + j] = acc;
}
__global__ void fold_wv(const float* __restrict__ Wv) {
    int g = blockIdx.x * blockDim.x + threadIdx.x;
    int j = g & 63;
    int h = (g >> 6) & (NH - 1);
    int d = g >> 10;
    const float* wrow = Wv + (size_t)d * ND + h * 64;
    float acc = 0.f;
#pragma unroll 8
    for (int i = 0; i < 64; i++)
        acc += wrow[i] * g_R[i * 64 + j];
    g_Wvp[g] = acc;
}

// ---------------- fp16 preparation ------------------------------------------
__global__ void prep_a(const float* __restrict__ X, __half* __restrict__ A, int n2) {
    int g = blockIdx.x * blockDim.x + threadIdx.x;
    if (g >= n2) return;
    float2 v = *(const float2*)&X[2 * g];
    *(uint32_t*)&A[2 * g] = pack_f16(v.x, v.y);
}
// W2[n,k] = fp16(W[k,n])  (transpose)
__global__ void prep_w(const float* __restrict__ W, __half* __restrict__ W2) {
    __shared__ float t[32][33];
    int k0 = blockIdx.y * 32, n0 = blockIdx.x * 32;
    int tx = threadIdx.x, ty = threadIdx.y;
#pragma unroll
    for (int i = 0; i < 32; i += 8)
        t[ty + i][tx] = W[(size_t)(k0 + ty + i) * ND + n0 + tx];
    __syncthreads();
#pragma unroll
    for (int i = 0; i < 32; i += 8) {
        int n = n0 + ty + i, k = k0 + tx;
        W2[(size_t)n * ND + k] = __float2half(t[tx][ty + i]);
    }
}

// ---------------- HMMA GEMM: 128x128x32 tile, 4 warps (2x2 of 64x64) --------
// EPI: 1 = f32 store + bias, 2 = QKV fp16 store
#define GST 10240                      // bytes per stage per operand (128*40*2)
#define GSMEM_B (6 * GST)              // 61440 bytes

template<int EPI>
__global__ __launch_bounds__(128)
void gemm_mma(const __half* __restrict__ A, const __half* __restrict__ B,
              float* __restrict__ C, const float* __restrict__ bias, int Ncols)
{
    extern __shared__ __half gsm[];
    const uint32_t sbase = smem_u32(gsm);
    const int tid = threadIdx.x, lane = tid & 31, wid = tid >> 5;
    const int wm = wid >> 1, wn = wid & 1;
    const int m0 = blockIdx.y * 128, n0 = blockIdx.x * 128;
    const __half* Ap = A + (size_t)m0 * ND;
    const __half* Bp = B + (size_t)n0 * ND;

#define G_LOAD(st, ch)                                                        \
    do {                                                                      \
        uint32_t _sA = sbase + (st) * GST;                                    \
        uint32_t _sB = sbase + 3 * GST + (st) * GST;                          \
        const __half* _ag = Ap + (ch) * 32;                                   \
        const __half* _bg = Bp + (ch) * 32;                                   \
        _Pragma("unroll")                                                     \
        for (int _i = 0; _i < 4; _i++) {                                      \
            int _idx = _i * 128 + tid;                                        \
            int _r = _idx >> 2, _sg = _idx & 3;                               \
            uint32_t _o = (uint32_t)(_r * 80 + _sg * 16);                     \
            CPA16(_sA + _o, _ag + (size_t)_r * ND + _sg * 8);                 \
            CPA16(_sB + _o, _bg + (size_t)_r * ND + _sg * 8);                 \
        }                                                                     \
        CPCOMMIT();                                                           \
    } while (0)

    float acc[4][8][4];
#pragma unroll
    for (int i = 0; i < 4; i++)
#pragma unroll
        for (int j = 0; j < 8; j++)
#pragma unroll
            for (int k = 0; k < 4; k++) acc[i][j][k] = 0.f;

    G_LOAD(0, 0);
    G_LOAD(1, 1);

    for (int c = 0; c < NCHUNK; c++) {
        if (c < NCHUNK - 1) CPWAIT1(); else CPWAIT0();
        __syncthreads();
        if (c + 2 < NCHUNK) G_LOAD((c + 2) % 3, c + 2);

        int st = c % 3;
        uint32_t sA = sbase + st * GST;
        uint32_t sB = sbase + 3 * GST + st * GST;
#pragma unroll
        for (int kk = 0; kk < 2; kk++) {
            uint32_t a[4][4], b[8][2];
#pragma unroll
            for (int mi = 0; mi < 4; mi++) {
                uint32_t ad = sA + (uint32_t)((wm * 64 + mi * 16 + (lane & 15)) * 80
                                              + kk * 32 + (lane >> 4) * 16);
                LDSM4(a[mi], ad);
            }
#pragma unroll
            for (int pr = 0; pr < 4; pr++) {
                uint32_t t4[4];
                uint32_t bd = sB + (uint32_t)((wn * 64 + pr * 16 + ((lane >> 4) & 1) * 8
                                               + (lane & 7)) * 80
                                              + kk * 32 + ((lane >> 3) & 1) * 16);
                LDSM4(t4, bd);
                b[2 * pr][0] = t4[0]; b[2 * pr][1] = t4[1];
                b[2 * pr + 1][0] = t4[2]; b[2 * pr + 1][1] = t4[3];
            }
#pragma unroll
            for (int mi = 0; mi < 4; mi++)
#pragma unroll
                for (int ni = 0; ni < 8; ni++)
                    MMA_F16(acc[mi][ni], a[mi], b[ni]);
        }
    }

    if (EPI == 2) {
        // write Q/K/V fp16 directly; arr uniform per CTA
        const int arr = n0 >> 10;
        __half* hb = (arr == 0) ? g_Qs : (arr == 1) ? g_Ks : g_Vs;
        const float sc = (arr == 0) ? QSCALE : 1.f;
#pragma unroll
        for (int mi = 0; mi < 4; mi++)
#pragma unroll
            for (int ni = 0; ni < 8; ni++) {
                int row = m0 + wm * 64 + mi * 16 + (lane >> 2);
                int c = (n0 & 1023) + wn * 64 + ni * 8 + (lane & 3) * 2;
                size_t di = (size_t)row * ND + c;
                *(uint32_t*)&hb[di] = pack_f16(acc[mi][ni][0] * sc, acc[mi][ni][1] * sc);
                *(uint32_t*)&hb[di + (size_t)8 * ND] =
                    pack_f16(acc[mi][ni][2] * sc, acc[mi][ni][3] * sc);
            }
    } else {
#pragma unroll
        for (int mi = 0; mi < 4; mi++)
#pragma unroll
            for (int ni = 0; ni < 8; ni++) {
                int row = m0 + wm * 64 + mi * 16 + (lane >> 2);
                int col = n0 + wn * 64 + ni * 8 + (lane & 3) * 2;
                float b0 = bias[col], b1 = bias[col + 1];
                float2 v0 = { acc[mi][ni][0] + b0, acc[mi][ni][1] + b1 };
                float2 v1 = { acc[mi][ni][2] + b0, acc[mi][ni][3] + b1 };
                *(float2*)&C[(size_t)row * Ncols + col] = v0;
                *(float2*)&C[(size_t)(row + 8) * Ncols + col] = v1;
            }
    }
#undef G_LOAD
}

// ---------------- HMMA flash attention (fp16 single-pass) -------------------
// Br=128 (4 warps x 32 rows), Bc=64, hd=64, double-buffered KV.
// smem bytes: Q 128*144=18432; per stage {K,V} 2*64*144=18432; 2 stages.
#define FQB   18432
#define FKVB  9216
#define FA_SMEM_B (FQB + 2 * 2 * FKVB)   // 55296

__global__ __launch_bounds__(128)
void flash_mma() {
    extern __shared__ __half fsm[];
    const uint32_t sbase = smem_u32(fsm);
    const uint32_t sQ = sbase;
    const uint32_t sKV0 = sbase + FQB;

    const int tid = threadIdx.x, lane = tid & 31, wid = tid >> 5;
    const int b = blockIdx.y >> 4, h = blockIdx.y & 15;
    const int q0 = blockIdx.x * 128;
    const int wq = wid * 32;
    const size_t base = ((size_t)b * NT) * ND + (size_t)h * NHD;

    const __half* gs[2] = { g_Ks + base, g_Vs + base };

#define KV_LOAD(stg, kv0)                                                     \
    do {                                                                      \
        uint32_t _sd = sKV0 + (stg) * (2 * FKVB);                             \
        _Pragma("unroll")                                                     \
        for (int _i = 0; _i < 8; _i++) {                                      \
            int _idx = _i * 128 + tid;                                        \
            int _arr = _idx >> 9, _rem = _idx & 511;                          \
            int _r = _rem >> 3, _sg = _rem & 7;                               \
            CPA16(_sd + (uint32_t)(_arr * FKVB + _r * 144 + _sg * 16),        \
                  gs[_arr] + (size_t)((kv0) + _r) * ND + _sg * 8);            \
        }                                                                     \
        CPCOMMIT();                                                           \
    } while (0)

    // Q load — same commit group as KV tile 0
    {
        const __half* qp = g_Qs + base;
#pragma unroll
        for (int i = 0; i < 8; i++) {
            int idx = i * 128 + tid;
            int r = idx >> 3, sg = idx & 7;
            CPA16(sQ + (uint32_t)(r * 144 + sg * 16),
                  qp + (size_t)(q0 + r) * ND + sg * 8);
        }
    }
    KV_LOAD(0, 0);
    KV_LOAD(1, 64);

    float o[2][8][4];
    float mrow[2][2], lrow[2][2];
#pragma unroll
    for (int mi = 0; mi < 2; mi++) {
        mrow[mi][0] = mrow[mi][1] = -1e30f;
        lrow[mi][0] = lrow[mi][1] = 0.f;
#pragma unroll
        for (int nd = 0; nd < 8; nd++)
#pragma unroll
            for (int k = 0; k < 4; k++) o[mi][nd][k] = 0.f;
    }

    for (int t = 0; t < NT / 64; t++) {
        if (t < NT / 64 - 1) CPWAIT1(); else CPWAIT0();
        __syncthreads();
        const uint32_t sK = sKV0 + (t & 1) * (2 * FKVB);
        const uint32_t sV = sK + FKVB;

        // ---- S = Q K^T ----
        float s[2][8][4];
#pragma unroll
        for (int mi = 0; mi < 2; mi++)
#pragma unroll
            for (int ni = 0; ni < 8; ni++)
#pragma unroll
                for (int k = 0; k < 4; k++) s[mi][ni][k] = 0.f;

#pragma unroll
        for (int kk = 0; kk < 4; kk++) {
            uint32_t aq[2][4];
#pragma unroll
            for (int mi = 0; mi < 2; mi++) {
                uint32_t off = (uint32_t)((wq + mi * 16 + (lane & 15)) * 144
                                          + kk * 32 + (lane >> 4) * 16);
                LDSM4(aq[mi], sQ + off);
            }
            uint32_t bk[8][2];
#pragma unroll
            for (int pr = 0; pr < 4; pr++) {
                uint32_t off = (uint32_t)((pr * 16 + ((lane >> 4) & 1) * 8 + (lane & 7)) * 144
                                          + kk * 32 + ((lane >> 3) & 1) * 16);
                uint32_t t4[4];
                LDSM4(t4, sK + off);
                bk[2 * pr][0] = t4[0]; bk[2 * pr][1] = t4[1];
                bk[2 * pr + 1][0] = t4[2]; bk[2 * pr + 1][1] = t4[3];
            }
#pragma unroll
            for (int mi = 0; mi < 2; mi++)
#pragma unroll
                for (int ni = 0; ni < 8; ni++)
                    MMA_F16(s[mi][ni], aq[mi], bk[ni]);
        }

        // ---- online softmax (exp2 domain; scale folded into Q) ----
#pragma unroll
        for (int mi = 0; mi < 2; mi++)
#pragma unroll
            for (int hf = 0; hf < 2; hf++) {
                float vmax = -1e30f;
#pragma unroll
                for (int ni = 0; ni < 8; ni++)
                    vmax = fmaxf(vmax, fmaxf(s[mi][ni][2 * hf], s[mi][ni][2 * hf + 1]));
                vmax = fmaxf(vmax, __shfl_xor_sync(0xffffffffu, vmax, 1));
                vmax = fmaxf(vmax, __shfl_xor_sync(0xffffffffu, vmax, 2));
                float mo = mrow[mi][hf];
                float mn = fmaxf(mo, vmax);
                float corr = exp2f(mo - mn);
                mrow[mi][hf] = mn;
                float rs = 0.f;
#pragma unroll
                for (int ni = 0; ni < 8; ni++) {
                    float p0 = exp2f(s[mi][ni][2 * hf] - mn);
                    float p1 = exp2f(s[mi][ni][2 * hf + 1] - mn);
                    s[mi][ni][2 * hf] = p0;
                    s[mi][ni][2 * hf + 1] = p1;
                    rs += p0 + p1;
                }
                rs += __shfl_xor_sync(0xffffffffu, rs, 1);
                rs += __shfl_xor_sync(0xffffffffu, rs, 2);
                lrow[mi][hf] = lrow[mi][hf] * corr + rs;
#pragma unroll
                for (int ni = 0; ni < 8; ni++) {
                    o[mi][ni][2 * hf] *= corr;
                    o[mi][ni][2 * hf + 1] *= corr;
                }
            }

        // ---- O += P V ----
#pragma unroll
        for (int kk = 0; kk < 4; kk++) {
            uint32_t bv[8][2];
#pragma unroll
            for (int q = 0; q < 4; q++) {
                uint32_t off = (uint32_t)((kk * 16 + ((lane >> 3) & 1) * 8 + (lane & 7)) * 144
                                          + q * 32 + ((lane >> 4) & 1) * 16);
                uint32_t t4[4];
                LDSM4T(t4, sV + off);
                bv[2 * q][0] = t4[0]; bv[2 * q][1] = t4[1];
                bv[2 * q + 1][0] = t4[2]; bv[2 * q + 1][1] = t4[3];
            }
#pragma unroll
            for (int mi = 0; mi < 2; mi++) {
                const float* p0 = s[mi][2 * kk];
                const float* p1 = s[mi][2 * kk + 1];
                uint32_t ap[4];
                ap[0] = pack_f16(p0[0], p0[1]);
                ap[1] = pack_f16(p0[2], p0[3]);
                ap[2] = pack_f16(p1[0], p1[1]);
                ap[3] = pack_f16(p1[2], p1[3]);
#pragma unroll
                for (int nd = 0; nd < 8; nd++)
                    MMA_F16(o[mi][nd], ap, bv[nd]);
            }
        }

        // ---- prefetch KV tile t+2 into the buffer we just consumed ----
        if (t + 2 < NT / 64) {
            __syncthreads();
            KV_LOAD(t & 1, (t + 2) * 64);
        }
    }

    // ---- epilogue: write fp16 activations for the output projection ----
#pragma unroll
    for (int mi = 0; mi < 2; mi++)
#pragma unroll
        for (int hf = 0; hf < 2; hf++) {
            float inv = 1.f / lrow[mi][hf];
            int m = b * NT + q0 + wq + mi * 16 + (lane >> 2) + hf * 8;
#pragma unroll
            for (int nd = 0; nd < 8; nd++) {
                int k = h * 64 + nd * 8 + (lane & 3) * 2;
                *(uint32_t*)&g_A[(size_t)m * ND + k] =
                    pack_f16(o[mi][nd][2 * hf] * inv, o[mi][nd][2 * hf + 1] * inv);
            }
        }
#undef KV_LOAD
}

// ---------------- host launcher --------------------------------------------
extern "C" void kernel_launch(void* const* d_in, const int* in_sizes, int n_in,
                              void* d_out, int out_size) {
    (void)in_sizes; (void)n_in; (void)out_size;
    const float* x  = (const float*)d_in[0];
    const float* Wq = (const float*)d_in[1];
    const float* Wk = (const float*)d_in[2];
    const float* Wv = (const float*)d_in[3];
    const float* Wo = (const float*)d_in[4];
    const float* bo = (const float*)d_in[5];
    float* out = (float*)d_out;

    float *Wvpp;
    __half *Aap, *Wp, *Wop;
    cudaGetSymbolAddress((void**)&Wvpp, g_Wvp);
    cudaGetSymbolAddress((void**)&Aap, g_A);
    cudaGetSymbolAddress((void**)&Wp, g_W);
    cudaGetSymbolAddress((void**)&Wop, g_Wo);

    rope_build<<<(NT * NHD + 255) / 256, 256>>>();
    compute_R<<<(NHD * NHD) / 256, 256>>>();
    fold_wv<<<(ND * ND) / 256, 256>>>(Wv);

    prep_a<<<(NBT * ND / 2) / 256, 256>>>(x, Aap, NBT * ND / 2);
    dim3 pwg(32, 32), pwb(32, 8);
    prep_w<<<pwg, pwb>>>(Wq, Wp);
    prep_w<<<pwg, pwb>>>(Wk, Wp + (size_t)ND * ND);
    prep_w<<<pwg, pwb>>>(Wvpp, Wp + (size_t)2 * ND * ND);
    prep_w<<<pwg, pwb>>>(Wo, Wop);

    cudaFuncSetAttribute(gemm_mma<1>, cudaFuncAttributeMaxDynamicSharedMemorySize, GSMEM_B);
    cudaFuncSetAttribute(gemm_mma<2>, cudaFuncAttributeMaxDynamicSharedMemorySize, GSMEM_B);

    // fused QKV projection with fp16 epilogue: [4096, 3072] = A @ W^T
    gemm_mma<2><<<dim3(3072 / 128, NBT / 128), 128, GSMEM_B>>>(Aap, Wp, nullptr, nullptr, 0);

    cudaFuncSetAttribute(flash_mma, cudaFuncAttributeMaxDynamicSharedMemorySize, FA_SMEM_B);
    flash_mma<<<dim3(NT / 128, NB * NH), 128, FA_SMEM_B>>>();

    // output projection + bias (reads g_A written by flash epilogue)
    gemm_mma<1><<<dim3(ND / 128, NBT / 128), 128, GSMEM_B>>>(Aap, Wop, out, bo, ND);
}

// round 7
// speedup vs baseline: 5.6464x; 1.0539x over previous
#include <cuda_runtime.h>
#include <cuda_fp16.h>
#include <cstdint>
#include <math.h>

#define NB 2
#define NT 2048
#define ND 1024
#define NH 16
#define NHD 64
#define NBT (NB*NT)
#define NCHUNK (ND/32)     // 32 chunks of BK=32
#define QSCALE 0.18033688011111772f   // 0.125 * log2(e)

// ---------------- scratch ---------------------------------------------------
__device__ __half g_A[(size_t)NBT*ND];          // fp16 activations (x, later o)
__device__ __half g_W[(size_t)3*ND*ND];         // [n,k] fp16 Wq|Wk|Wv'
__device__ __half g_Wo[(size_t)ND*ND];          // [n,k] fp16 Wo
__device__ float g_rope[(size_t)NT*NHD];
__device__ float g_R[NHD*NHD];
__device__ float g_Wvp[(size_t)ND*ND];
__device__ __half g_Qs[(size_t)NBT*ND];         // q * QSCALE
__device__ __half g_Ks[(size_t)NBT*ND];
__device__ __half g_Vs[(size_t)NBT*ND];

// ---------------- helpers ---------------------------------------------------
__device__ __forceinline__ uint32_t smem_u32(const void* p) {
    uint32_t a;
    asm("{ .reg .u64 t; cvta.to.shared.u64 t, %1; cvt.u32.u64 %0, t; }"
        : "=r"(a) : "l"(p));
    return a;
}
__device__ __forceinline__ float ex2(float x) {
    float r;
    asm("ex2.approx.ftz.f32 %0, %1;" : "=f"(r) : "f"(x));
    return r;
}
#define CPA16(s, g) asm volatile("cp.async.cg.shared.global [%0], [%1], 16;\n" :: "r"(s), "l"(g))
#define CPCOMMIT()  asm volatile("cp.async.commit_group;\n" ::: "memory")
#define CPWAIT0()   asm volatile("cp.async.wait_group 0;\n" ::: "memory")
#define CPWAIT1()   asm volatile("cp.async.wait_group 1;\n" ::: "memory")

#define LDSM4(r, addr)                                                        \
    asm volatile("ldmatrix.sync.aligned.m8n8.x4.shared.b16 {%0,%1,%2,%3}, [%4];" \
                 : "=r"((r)[0]), "=r"((r)[1]), "=r"((r)[2]), "=r"((r)[3])     \
                 : "r"(addr))
#define LDSM4T(r, addr)                                                       \
    asm volatile("ldmatrix.sync.aligned.m8n8.x4.trans.shared.b16 {%0,%1,%2,%3}, [%4];" \
                 : "=r"((r)[0]), "=r"((r)[1]), "=r"((r)[2]), "=r"((r)[3])     \
                 : "r"(addr))
#define MMA_F16(d, a, b)                                                      \
    asm volatile("mma.sync.aligned.m16n8k16.row.col.f32.f16.f16.f32 "         \
                 "{%0,%1,%2,%3},{%4,%5,%6,%7},{%8,%9},{%0,%1,%2,%3};"         \
                 : "+f"((d)[0]), "+f"((d)[1]), "+f"((d)[2]), "+f"((d)[3])     \
                 : "r"((a)[0]), "r"((a)[1]), "r"((a)[2]), "r"((a)[3]),        \
                   "r"((b)[0]), "r"((b)[1]))

// packs (lo_val -> lower half, hi_val -> upper half)
__device__ __forceinline__ uint32_t pack_f16(float lo, float hi) {
    uint32_t r;
    asm("cvt.rn.f16x2.f32 %0, %1, %2;" : "=r"(r) : "f"(hi), "f"(lo));
    return r;
}

// ---------------- rope / R / fold -------------------------------------------
__global__ void rope_build() {
    int g = blockIdx.x * blockDim.x + threadIdx.x;
    if (g >= NT * NHD) return;
    int s = g >> 6, i = g & 63, k = i & 31;
    double inv = exp(-(double)k * (log(10000.0) / 32.0));
    double ph = fmod((double)s * inv, 6.283185307179586);
    float phf = (float)ph;
    g_rope[g] = (i < 32) ? cosf(phf) : sinf(phf);
}
// R[i][j] = sum_s rope[s,i]*rope[s,j]; one block per (i,j)
__global__ __launch_bounds__(128) void compute_R() {
    __shared__ float red[4];
    const int i = blockIdx.x >> 6, j = blockIdx.x & 63;
    const int t = threadIdx.x;
    float acc = 0.f;
#pragma unroll 4
    for (int s = t; s < NT; s += 128)
        acc += g_rope[s * 64 + i] * g_rope[s * 64 + j];
    acc += __shfl_xor_sync(0xffffffffu, acc, 16);
    acc += __shfl_xor_sync(0xffffffffu, acc, 8);
    acc += __shfl_xor_sync(0xffffffffu, acc, 4);
    acc += __shfl_xor_sync(0xffffffffu, acc, 2);
    acc += __shfl_xor_sync(0xffffffffu, acc, 1);
    if ((t & 31) == 0) red[t >> 5] = acc;
    __syncthreads();
    if (t == 0) g_R[blockIdx.x] = (red[0] + red[1]) + (red[2] + red[3]);
}
__global__ void fold_wv(const float* __restrict__ Wv) {
    int g = blockIdx.x * blockDim.x + threadIdx.x;
    int j = g & 63;
    int h = (g >> 6) & (NH - 1);
    int d = g >> 10;
    const float* wrow = Wv + (size_t)d * ND + h * 64;
    float acc = 0.f;
#pragma unroll 8
    for (int i = 0; i < 64; i++)
        acc += wrow[i] * g_R[i * 64 + j];
    g_Wvp[g] = acc;
}

// ---------------- fp16 preparation ------------------------------------------
__global__ void prep_a(const float* __restrict__ X, __half* __restrict__ A, int n4) {
    int g = blockIdx.x * blockDim.x + threadIdx.x;
    if (g >= n4) return;
    float4 v = ((const float4*)X)[g];
    uint2 o;
    o.x = pack_f16(v.x, v.y);
    o.y = pack_f16(v.z, v.w);
    ((uint2*)A)[g] = o;
}
// transpose + fp16 convert all four weights in one launch (z selects source)
__global__ void prep_w4(const float* __restrict__ Wq, const float* __restrict__ Wk,
                        const float* __restrict__ Wo) {
    __shared__ float t[32][33];
    const int z = blockIdx.z;
    const float* W = (z == 0) ? Wq : (z == 1) ? Wk : (z == 2) ? g_Wvp : Wo;
    __half* dst = (z < 3) ? (g_W + (size_t)z * ND * ND) : g_Wo;
    int k0 = blockIdx.y * 32, n0 = blockIdx.x * 32;
    int tx = threadIdx.x, ty = threadIdx.y;
#pragma unroll
    for (int i = 0; i < 32; i += 8)
        t[ty + i][tx] = W[(size_t)(k0 + ty + i) * ND + n0 + tx];
    __syncthreads();
#pragma unroll
    for (int i = 0; i < 32; i += 8) {
        int n = n0 + ty + i, k = k0 + tx;
        dst[(size_t)n * ND + k] = __float2half(t[tx][ty + i]);
    }
}

// ---------------- HMMA GEMM: 128x128x32 tile, 4 warps (2x2 of 64x64) --------
// EPI: 1 = f32 store + bias, 2 = QKV fp16 store
#define GST 10240                      // bytes per stage per operand (128*40*2)
#define GSMEM_B (6 * GST)              // 61440 bytes

template<int EPI>
__global__ __launch_bounds__(128)
void gemm_mma(const __half* __restrict__ A, const __half* __restrict__ B,
              float* __restrict__ C, const float* __restrict__ bias, int Ncols)
{
    extern __shared__ __half gsm[];
    const uint32_t sbase = smem_u32(gsm);
    const int tid = threadIdx.x, lane = tid & 31, wid = tid >> 5;
    const int wm = wid >> 1, wn = wid & 1;
    const int m0 = blockIdx.y * 128, n0 = blockIdx.x * 128;
    const __half* Ap = A + (size_t)m0 * ND;
    const __half* Bp = B + (size_t)n0 * ND;

#define G_LOAD(st, ch)                                                        \
    do {                                                                      \
        uint32_t _sA = sbase + (st) * GST;                                    \
        uint32_t _sB = sbase + 3 * GST + (st) * GST;                          \
        const __half* _ag = Ap + (ch) * 32;                                   \
        const __half* _bg = Bp + (ch) * 32;                                   \
        _Pragma("unroll")                                                     \
        for (int _i = 0; _i < 4; _i++) {                                      \
            int _idx = _i * 128 + tid;                                        \
            int _r = _idx >> 2, _sg = _idx & 3;                               \
            uint32_t _o = (uint32_t)(_r * 80 + _sg * 16);                     \
            CPA16(_sA + _o, _ag + (size_t)_r * ND + _sg * 8);                 \
            CPA16(_sB + _o, _bg + (size_t)_r * ND + _sg * 8);                 \
        }                                                                     \
        CPCOMMIT();                                                           \
    } while (0)

    float acc[4][8][4];
#pragma unroll
    for (int i = 0; i < 4; i++)
#pragma unroll
        for (int j = 0; j < 8; j++)
#pragma unroll
            for (int k = 0; k < 4; k++) acc[i][j][k] = 0.f;

    G_LOAD(0, 0);
    G_LOAD(1, 1);

    for (int c = 0; c < NCHUNK; c++) {
        if (c < NCHUNK - 1) CPWAIT1(); else CPWAIT0();
        __syncthreads();
        if (c + 2 < NCHUNK) G_LOAD((c + 2) % 3, c + 2);

        int st = c % 3;
        uint32_t sA = sbase + st * GST;
        uint32_t sB = sbase + 3 * GST + st * GST;
#pragma unroll
        for (int kk = 0; kk < 2; kk++) {
            uint32_t a[4][4], b[8][2];
#pragma unroll
            for (int mi = 0; mi < 4; mi++) {
                uint32_t ad = sA + (uint32_t)((wm * 64 + mi * 16 + (lane & 15)) * 80
                                              + kk * 32 + (lane >> 4) * 16);
                LDSM4(a[mi], ad);
            }
#pragma unroll
            for (int pr = 0; pr < 4; pr++) {
                uint32_t t4[4];
                uint32_t bd = sB + (uint32_t)((wn * 64 + pr * 16 + ((lane >> 4) & 1) * 8
                                               + (lane & 7)) * 80
                                              + kk * 32 + ((lane >> 3) & 1) * 16);
                LDSM4(t4, bd);
                b[2 * pr][0] = t4[0]; b[2 * pr][1] = t4[1];
                b[2 * pr + 1][0] = t4[2]; b[2 * pr + 1][1] = t4[3];
            }
#pragma unroll
            for (int mi = 0; mi < 4; mi++)
#pragma unroll
                for (int ni = 0; ni < 8; ni++)
                    MMA_F16(acc[mi][ni], a[mi], b[ni]);
        }
    }

    if (EPI == 2) {
        // write Q/K/V fp16 directly; arr uniform per CTA
        const int arr = n0 >> 10;
        __half* hb = (arr == 0) ? g_Qs : (arr == 1) ? g_Ks : g_Vs;
        const float sc = (arr == 0) ? QSCALE : 1.f;
#pragma unroll
        for (int mi = 0; mi < 4; mi++)
#pragma unroll
            for (int ni = 0; ni < 8; ni++) {
                int row = m0 + wm * 64 + mi * 16 + (lane >> 2);
                int c = (n0 & 1023) + wn * 64 + ni * 8 + (lane & 3) * 2;
                size_t di = (size_t)row * ND + c;
                *(uint32_t*)&hb[di] = pack_f16(acc[mi][ni][0] * sc, acc[mi][ni][1] * sc);
                *(uint32_t*)&hb[di + (size_t)8 * ND] =
                    pack_f16(acc[mi][ni][2] * sc, acc[mi][ni][3] * sc);
            }
    } else {
#pragma unroll
        for (int mi = 0; mi < 4; mi++)
#pragma unroll
            for (int ni = 0; ni < 8; ni++) {
                int row = m0 + wm * 64 + mi * 16 + (lane >> 2);
                int col = n0 + wn * 64 + ni * 8 + (lane & 3) * 2;
                float b0 = bias[col], b1 = bias[col + 1];
                float2 v0 = { acc[mi][ni][0] + b0, acc[mi][ni][1] + b1 };
                float2 v1 = { acc[mi][ni][2] + b0, acc[mi][ni][3] + b1 };
                *(float2*)&C[(size_t)row * Ncols + col] = v0;
                *(float2*)&C[(size_t)(row + 8) * Ncols + col] = v1;
            }
    }
#undef G_LOAD
}

// ---------------- HMMA flash attention (fp16 single-pass) -------------------
// Br=128 (4 warps x 32 rows), Bc=64, hd=64, double-buffered KV.
// smem bytes: Q 128*144=18432; per stage {K,V} 2*64*144=18432; 2 stages.
#define FQB   18432
#define FKVB  9216
#define FA_SMEM_B (FQB + 2 * 2 * FKVB)   // 55296

__global__ __launch_bounds__(128)
void flash_mma() {
    extern __shared__ __half fsm[];
    const uint32_t sbase = smem_u32(fsm);
    const uint32_t sQ = sbase;
    const uint32_t sKV0 = sbase + FQB;

    const int tid = threadIdx.x, lane = tid & 31, wid = tid >> 5;
    const int b = blockIdx.y >> 4, h = blockIdx.y & 15;
    const int q0 = blockIdx.x * 128;
    const int wq = wid * 32;
    const size_t base = ((size_t)b * NT) * ND + (size_t)h * NHD;

    const __half* gs[2] = { g_Ks + base, g_Vs + base };

#define KV_LOAD(stg, kv0)                                                     \
    do {                                                                      \
        uint32_t _sd = sKV0 + (stg) * (2 * FKVB);                             \
        _Pragma("unroll")                                                     \
        for (int _i = 0; _i < 8; _i++) {                                      \
            int _idx = _i * 128 + tid;                                        \
            int _arr = _idx >> 9, _rem = _idx & 511;                          \
            int _r = _rem >> 3, _sg = _rem & 7;                               \
            CPA16(_sd + (uint32_t)(_arr * FKVB + _r * 144 + _sg * 16),        \
                  gs[_arr] + (size_t)((kv0) + _r) * ND + _sg * 8);            \
        }                                                                     \
        CPCOMMIT();                                                           \
    } while (0)

    // Q load — same commit group as KV tile 0
    {
        const __half* qp = g_Qs + base;
#pragma unroll
        for (int i = 0; i < 8; i++) {
            int idx = i * 128 + tid;
            int r = idx >> 3, sg = idx & 7;
            CPA16(sQ + (uint32_t)(r * 144 + sg * 16),
                  qp + (size_t)(q0 + r) * ND + sg * 8);
        }
    }
    KV_LOAD(0, 0);
    KV_LOAD(1, 64);

    // ---- hoist Q fragments into registers (tile-invariant) ----
    CPWAIT1();          // group(Q + KV0) complete
    __syncthreads();
    uint32_t aq[4][2][4];
#pragma unroll
    for (int kk = 0; kk < 4; kk++)
#pragma unroll
        for (int mi = 0; mi < 2; mi++) {
            uint32_t off = (uint32_t)((wq + mi * 16 + (lane & 15)) * 144
                                      + kk * 32 + (lane >> 4) * 16);
            LDSM4(aq[kk][mi], sQ + off);
        }

    float o[2][8][4];
    float mrow[2][2], lrow[2][2];
#pragma unroll
    for (int mi = 0; mi < 2; mi++) {
        mrow[mi][0] = mrow[mi][1] = -1e30f;
        lrow[mi][0] = lrow[mi][1] = 0.f;
#pragma unroll
        for (int nd = 0; nd < 8; nd++)
#pragma unroll
            for (int k = 0; k < 4; k++) o[mi][nd][k] = 0.f;
    }

    for (int t = 0; t < NT / 64; t++) {
        if (t < NT / 64 - 1) CPWAIT1(); else CPWAIT0();
        __syncthreads();
        const uint32_t sK = sKV0 + (t & 1) * (2 * FKVB);
        const uint32_t sV = sK + FKVB;

        // ---- S = Q K^T ----
        float s[2][8][4];
#pragma unroll
        for (int mi = 0; mi < 2; mi++)
#pragma unroll
            for (int ni = 0; ni < 8; ni++)
#pragma unroll
                for (int k = 0; k < 4; k++) s[mi][ni][k] = 0.f;

#pragma unroll
        for (int kk = 0; kk < 4; kk++) {
            uint32_t bk[8][2];
#pragma unroll
            for (int pr = 0; pr < 4; pr++) {
                uint32_t off = (uint32_t)((pr * 16 + ((lane >> 4) & 1) * 8 + (lane & 7)) * 144
                                          + kk * 32 + ((lane >> 3) & 1) * 16);
                uint32_t t4[4];
                LDSM4(t4, sK + off);
                bk[2 * pr][0] = t4[0]; bk[2 * pr][1] = t4[1];
                bk[2 * pr + 1][0] = t4[2]; bk[2 * pr + 1][1] = t4[3];
            }
#pragma unroll
            for (int mi = 0; mi < 2; mi++)
#pragma unroll
                for (int ni = 0; ni < 8; ni++)
                    MMA_F16(s[mi][ni], aq[kk][mi], bk[ni]);
        }

        // ---- online softmax (exp2 domain; scale folded into Q) ----
#pragma unroll
        for (int mi = 0; mi < 2; mi++)
#pragma unroll
            for (int hf = 0; hf < 2; hf++) {
                float vmax = -1e30f;
#pragma unroll
                for (int ni = 0; ni < 8; ni++)
                    vmax = fmaxf(vmax, fmaxf(s[mi][ni][2 * hf], s[mi][ni][2 * hf + 1]));
                vmax = fmaxf(vmax, __shfl_xor_sync(0xffffffffu, vmax, 1));
                vmax = fmaxf(vmax, __shfl_xor_sync(0xffffffffu, vmax, 2));
                float mo = mrow[mi][hf];
                float mn = fmaxf(mo, vmax);
                float corr = ex2(mo - mn);
                mrow[mi][hf] = mn;
                float rs = 0.f;
#pragma unroll
                for (int ni = 0; ni < 8; ni++) {
                    float p0 = ex2(s[mi][ni][2 * hf] - mn);
                    float p1 = ex2(s[mi][ni][2 * hf + 1] - mn);
                    s[mi][ni][2 * hf] = p0;
                    s[mi][ni][2 * hf + 1] = p1;
                    rs += p0 + p1;
                }
                rs += __shfl_xor_sync(0xffffffffu, rs, 1);
                rs += __shfl_xor_sync(0xffffffffu, rs, 2);
                lrow[mi][hf] = lrow[mi][hf] * corr + rs;
#pragma unroll
                for (int ni = 0; ni < 8; ni++) {
                    o[mi][ni][2 * hf] *= corr;
                    o[mi][ni][2 * hf + 1] *= corr;
                }
            }

        // ---- O += P V ----
#pragma unroll
        for (int kk = 0; kk < 4; kk++) {
            uint32_t bv[8][2];
#pragma unroll
            for (int q = 0; q < 4; q++) {
                uint32_t off = (uint32_t)((kk * 16 + ((lane >> 3) & 1) * 8 + (lane & 7)) * 144
                                          + q * 32 + ((lane >> 4) & 1) * 16);
                uint32_t t4[4];
                LDSM4T(t4, sV + off);
                bv[2 * q][0] = t4[0]; bv[2 * q][1] = t4[1];
                bv[2 * q + 1][0] = t4[2]; bv[2 * q + 1][1] = t4[3];
            }
#pragma unroll
            for (int mi = 0; mi < 2; mi++) {
                const float* p0 = s[mi][2 * kk];
                const float* p1 = s[mi][2 * kk + 1];
                uint32_t ap[4];
                ap[0] = pack_f16(p0[0], p0[1]);
                ap[1] = pack_f16(p0[2], p0[3]);
                ap[2] = pack_f16(p1[0], p1[1]);
                ap[3] = pack_f16(p1[2], p1[3]);
#pragma unroll
                for (int nd = 0; nd < 8; nd++)
                    MMA_F16(o[mi][nd], ap, bv[nd]);
            }
        }

        // ---- prefetch KV tile t+2 into the buffer we just consumed ----
        if (t + 2 < NT / 64) {
            __syncthreads();
            KV_LOAD(t & 1, (t + 2) * 64);
        }
    }

    // ---- epilogue: write fp16 activations for the output projection ----
#pragma unroll
    for (int mi = 0; mi < 2; mi++)
#pragma unroll
        for (int hf = 0; hf < 2; hf++) {
            float inv = 1.f / lrow[mi][hf];
            int m = b * NT + q0 + wq + mi * 16 + (lane >> 2) + hf * 8;
#pragma unroll
            for (int nd = 0; nd < 8; nd++) {
                int k = h * 64 + nd * 8 + (lane & 3) * 2;
                *(uint32_t*)&g_A[(size_t)m * ND + k] =
                    pack_f16(o[mi][nd][2 * hf] * inv, o[mi][nd][2 * hf + 1] * inv);
            }
        }
#undef KV_LOAD
}

// ---------------- host launcher --------------------------------------------
extern "C" void kernel_launch(void* const* d_in, const int* in_sizes, int n_in,
                              void* d_out, int out_size) {
    (void)in_sizes; (void)n_in; (void)out_size;
    const float* x  = (const float*)d_in[0];
    const float* Wq = (const float*)d_in[1];
    const float* Wk = (const float*)d_in[2];
    const float* Wv = (const float*)d_in[3];
    const float* Wo = (const float*)d_in[4];
    const float* bo = (const float*)d_in[5];
    float* out = (float*)d_out;

    __half *Aap;
    cudaGetSymbolAddress((void**)&Aap, g_A);

    rope_build<<<(NT * NHD + 255) / 256, 256>>>();
    compute_R<<<NHD * NHD, 128>>>();
    fold_wv<<<(ND * ND) / 256, 256>>>(Wv);

    prep_a<<<(NBT * ND / 4 + 255) / 256, 256>>>(x, Aap, NBT * ND / 4);
    prep_w4<<<dim3(32, 32, 4), dim3(32, 8)>>>(Wq, Wk, Wo);

    __half *Wp, *Wop;
    cudaGetSymbolAddress((void**)&Wp, g_W);
    cudaGetSymbolAddress((void**)&Wop, g_Wo);

    cudaFuncSetAttribute(gemm_mma<1>, cudaFuncAttributeMaxDynamicSharedMemorySize, GSMEM_B);
    cudaFuncSetAttribute(gemm_mma<2>, cudaFuncAttributeMaxDynamicSharedMemorySize, GSMEM_B);

    // fused QKV projection with fp16 epilogue: [4096, 3072] = A @ W^T
    gemm_mma<2><<<dim3(3072 / 128, NBT / 128), 128, GSMEM_B>>>(Aap, Wp, nullptr, nullptr, 0);

    cudaFuncSetAttribute(flash_mma, cudaFuncAttributeMaxDynamicSharedMemorySize, FA_SMEM_B);
    flash_mma<<<dim3(NT / 128, NB * NH), 128, FA_SMEM_B>>>();

    // output projection + bias (reads g_A written by flash epilogue)
    gemm_mma<1><<<dim3(ND / 128, NBT / 128), 128, GSMEM_B>>>(Aap, Wop, out, bo, ND);
}